// round 5
// baseline (speedup 1.0000x reference)
#include <cuda_runtime.h>

#define D     128
#define NMAX  100000
#define EMAX  1600000
#define ESMAX 30000
#define NREL  16

// ---------------- device scratch (no allocations allowed) ----------------
__device__ float g_h[(size_t)NMAX * D];    // GEMM outputs (h1, then h2)
__device__ float g_a[(size_t)NMAX * D];    // aggregation buffer (x pre-relu, then z)
__device__ float g_dinv[NMAX];             // degree, then d^-1/2 in place
__device__ float g_norm[EMAX];             // per-edge norm
__device__ int   g_cnt[NREL];
__device__ int   g_cur[NREL];
__device__ int   g_perm[ESMAX];

// ---------------- small prep kernels ----------------
__global__ void zero_kernel(int n) {
    int i = blockIdx.x * blockDim.x + threadIdx.x;
    if (i < n) g_dinv[i] = 0.0f;
    if (i < NREL) g_cnt[i] = 0;
}

__global__ void deg_kernel(const int* __restrict__ dst, int E) {
    int i = blockIdx.x * blockDim.x + threadIdx.x;
    if (i < E) atomicAdd(&g_dinv[dst[i]], 1.0f);
}

__global__ void dinv_kernel(int n) {
    int i = blockIdx.x * blockDim.x + threadIdx.x;
    if (i < n) {
        float d = g_dinv[i];
        g_dinv[i] = (d > 0.0f) ? (1.0f / sqrtf(d)) : 0.0f;
    }
}

__global__ void norm_kernel(const int* __restrict__ src, const int* __restrict__ dst, int E) {
    int i = blockIdx.x * blockDim.x + threadIdx.x;
    if (i < E) g_norm[i] = g_dinv[src[i]] * g_dinv[dst[i]];
}

// buf[n, D] = bias[D] broadcast (fuses the "+ b" of the conv)
__global__ void init_bias_kernel(float* __restrict__ buf, const float* __restrict__ bias, int total) {
    int i = blockIdx.x * blockDim.x + threadIdx.x;
    if (i < total) buf[i] = bias[i & (D - 1)];
}

// ---------------- fp32 GEMM: C[M,128] = op(A)[M,128] @ W[128,128] ----------------
// 128x128 output tile per 256-thread block, 8x8 microtile/thread, K-chunks of 32.
template <bool RELU>
__global__ __launch_bounds__(256, 2) void gemm_kernel(
    const float* __restrict__ A, const float* __restrict__ W,
    float* __restrict__ C, int M)
{
    __shared__ float As[32][D];   // transposed: As[k][m]
    __shared__ float Bs[32][D];   // Bs[k][n]
    const int tid = threadIdx.x;
    const int tx  = tid & 15;
    const int ty  = tid >> 4;
    const int base = blockIdx.x * 128;

    float acc[8][8];
#pragma unroll
    for (int i = 0; i < 8; i++)
#pragma unroll
        for (int j = 0; j < 8; j++) acc[i][j] = 0.0f;

#pragma unroll 1
    for (int kc = 0; kc < D; kc += 32) {
        // load A tile (128 rows x 32 k) transposed into As
#pragma unroll
        for (int it = 0; it < 4; it++) {
            int idx = tid + it * 256;          // 0..1023 float4s
            int r   = idx >> 3;                // row in tile
            int c4  = idx & 7;                 // float4 within 32-k slab
            int gr  = base + r;
            float4 v = make_float4(0.f, 0.f, 0.f, 0.f);
            if (gr < M) v = *(const float4*)(A + (size_t)gr * D + kc + c4 * 4);
            if (RELU) {
                v.x = fmaxf(v.x, 0.f); v.y = fmaxf(v.y, 0.f);
                v.z = fmaxf(v.z, 0.f); v.w = fmaxf(v.w, 0.f);
            }
            int kk = c4 * 4;
            As[kk + 0][r] = v.x; As[kk + 1][r] = v.y;
            As[kk + 2][r] = v.z; As[kk + 3][r] = v.w;
        }
        // load B tile (32 x 128), row-major, straight float4 copy
#pragma unroll
        for (int it = 0; it < 4; it++) {
            int idx = tid + it * 256;
            int k   = idx >> 5;
            int c4  = idx & 31;
            *(float4*)(&Bs[k][c4 * 4]) =
                *(const float4*)(W + (size_t)(kc + k) * D + c4 * 4);
        }
        __syncthreads();

#pragma unroll 8
        for (int k = 0; k < 32; k++) {
            float a[8], b[8];
            *(float4*)&a[0] = *(const float4*)&As[k][ty * 8];
            *(float4*)&a[4] = *(const float4*)&As[k][ty * 8 + 4];
            *(float4*)&b[0] = *(const float4*)&Bs[k][tx * 8];
            *(float4*)&b[4] = *(const float4*)&Bs[k][tx * 8 + 4];
#pragma unroll
            for (int i = 0; i < 8; i++)
#pragma unroll
                for (int j = 0; j < 8; j++)
                    acc[i][j] += a[i] * b[j];
        }
        __syncthreads();
    }

#pragma unroll
    for (int i = 0; i < 8; i++) {
        int gr = base + ty * 8 + i;
        if (gr < M) {
            *(float4*)(C + (size_t)gr * D + tx * 8) =
                make_float4(acc[i][0], acc[i][1], acc[i][2], acc[i][3]);
            *(float4*)(C + (size_t)gr * D + tx * 8 + 4) =
                make_float4(acc[i][4], acc[i][5], acc[i][6], acc[i][7]);
        }
    }
}

// ---------------- edge scatter: agg[dst] += norm * h[src] ----------------
// one warp per edge; lane handles 16B; vector reduction (sm_90+ red.v4.f32)
__global__ __launch_bounds__(256) void scatter_kernel(
    const float* __restrict__ h, const int* __restrict__ src,
    const int* __restrict__ dst, float* __restrict__ agg, int E)
{
    int gt   = blockIdx.x * blockDim.x + threadIdx.x;
    int e    = gt >> 5;
    int lane = gt & 31;
    if (e >= E) return;
    int   s = src[e];
    int   d = dst[e];
    float w = g_norm[e];
    float4 v = *(const float4*)(h + (size_t)s * D + lane * 4);
    v.x *= w; v.y *= w; v.z *= w; v.w *= w;
    float* p = agg + (size_t)d * D + lane * 4;
    asm volatile("red.global.add.v4.f32 [%0], {%1, %2, %3, %4};"
                 :: "l"(p), "f"(v.x), "f"(v.y), "f"(v.z), "f"(v.w) : "memory");
}

// ---------------- relation counting sort (16 bins) ----------------
__global__ void hist_kernel(const int* __restrict__ rel, int ES) {
    int i = blockIdx.x * blockDim.x + threadIdx.x;
    if (i < ES) atomicAdd(&g_cnt[rel[i]], 1);
}
__global__ void scan_kernel() {
    if (threadIdx.x == 0) {
        int s = 0;
        for (int r = 0; r < NREL; r++) { g_cur[r] = s; s += g_cnt[r]; }
    }
}
__global__ void perm_kernel(const int* __restrict__ rel, int ES) {
    int i = blockIdx.x * blockDim.x + threadIdx.x;
    if (i < ES) {
        int pos = atomicAdd(&g_cur[rel[i]], 1);
        g_perm[pos] = i;
    }
}

// ---------------- scoring: s = z[head]^T W[rel] z[tail] ----------------
// 16 relation-sorted triples per block; W_r cached in 64KB dynamic smem.
__global__ __launch_bounds__(128) void score_kernel(
    const float* __restrict__ z, const float* __restrict__ relW,
    const int* __restrict__ rel, const int* __restrict__ head,
    const int* __restrict__ tail, float* __restrict__ out, int ES)
{
    extern __shared__ float Ws[];       // 128*128 floats = 64KB
    __shared__ float zh[D];
    __shared__ float redbuf[4];
    const int tid = threadIdx.x;
    const int t0  = blockIdx.x * 16;

    const int r0 = rel[g_perm[t0]];
    {
        const float4* wsrc = (const float4*)(relW + (size_t)r0 * D * D);
        float4* wdst = (float4*)Ws;
#pragma unroll
        for (int i = tid; i < (D * D) / 4; i += 128) wdst[i] = wsrc[i];
    }
    __syncthreads();

    const int tend = min(t0 + 16, ES);
    for (int t = t0; t < tend; t++) {
        int idx = g_perm[t];
        int r   = rel[idx];
        int hh  = head[idx];
        int tt  = tail[idx];
        zh[tid] = z[(size_t)hh * D + tid];
        __syncthreads();

        float u = 0.f;
        if (r == r0) {
#pragma unroll 8
            for (int i = 0; i < D; i++) u += zh[i] * Ws[i * D + tid];
        } else {   // rare block-boundary case: read straight from L2
            const float* wg = relW + (size_t)r * D * D;
#pragma unroll 8
            for (int i = 0; i < D; i++) u += zh[i] * __ldg(&wg[i * D + tid]);
        }
        float p = u * z[(size_t)tt * D + tid];
#pragma unroll
        for (int o = 16; o > 0; o >>= 1)
            p += __shfl_down_sync(0xffffffffu, p, o);
        if ((tid & 31) == 0) redbuf[tid >> 5] = p;
        __syncthreads();
        if (tid == 0) out[idx] = redbuf[0] + redbuf[1] + redbuf[2] + redbuf[3];
        // no extra barrier needed: next zh write races with nothing (reads done
        // before the barrier above; redbuf rewritten only after the next one)
    }
}

// ---------------- launch ----------------
extern "C" void kernel_launch(void* const* d_in, const int* in_sizes, int n_in,
                              void* d_out, int out_size) {
    const float* x0   = (const float*)d_in[0];
    const float* W1   = (const float*)d_in[1];
    const float* b1   = (const float*)d_in[2];
    const float* W2   = (const float*)d_in[3];
    const float* b2   = (const float*)d_in[4];
    const float* relW = (const float*)d_in[5];
    const int*   edge = (const int*)  d_in[6];
    const int*   rel  = (const int*)  d_in[7];
    const int*   head = (const int*)  d_in[8];
    const int*   tail = (const int*)  d_in[9];
    float*       out  = (float*)d_out;

    const int N  = in_sizes[0] / D;
    const int E  = in_sizes[6] / 2;
    const int ES = in_sizes[7];
    const int* src = edge;
    const int* dst = edge + E;

    float *ph = nullptr, *pa = nullptr;
    cudaGetSymbolAddress((void**)&ph, g_h);
    cudaGetSymbolAddress((void**)&pa, g_a);

    const int T = 256;
    const int ND = N * D;
    const int sc_blocks = (int)(((long long)E * 32 + T - 1) / T);

    // degrees + symmetric norm
    zero_kernel<<<(N + T - 1) / T, T>>>(N);
    deg_kernel<<<(E + T - 1) / T, T>>>(dst, E);
    dinv_kernel<<<(N + T - 1) / T, T>>>(N);
    norm_kernel<<<(E + T - 1) / T, T>>>(src, dst, E);

    // layer 1: h1 = x0 @ W1 ; agg1 = b1 + scatter(norm * h1[src] -> dst)
    gemm_kernel<false><<<(N + 127) / 128, 256>>>(x0, W1, ph, N);
    init_bias_kernel<<<(ND + T - 1) / T, T>>>(pa, b1, ND);
    scatter_kernel<<<sc_blocks, T>>>(ph, src, dst, pa, E);

    // layer 2: h2 = relu(agg1) @ W2 ; z = b2 + scatter(norm * h2[src] -> dst)
    gemm_kernel<true><<<(N + 127) / 128, 256>>>(pa, W2, ph, N);
    init_bias_kernel<<<(ND + T - 1) / T, T>>>(pa, b2, ND);
    scatter_kernel<<<sc_blocks, T>>>(ph, src, dst, pa, E);

    // relation-sorted triple scoring
    hist_kernel<<<(ES + T - 1) / T, T>>>(rel, ES);
    scan_kernel<<<1, 32>>>();
    perm_kernel<<<(ES + T - 1) / T, T>>>(rel, ES);

    cudaFuncSetAttribute(score_kernel, cudaFuncAttributeMaxDynamicSharedMemorySize, 65536);
    score_kernel<<<(ES + 15) / 16, 128, 65536>>>(pa, relW, rel, head, tail, out, ES);
}

// round 7
// speedup vs baseline: 1.2057x; 1.2057x over previous
#include <cuda_runtime.h>

#define D     128
#define NMAX  100000
#define EMAX  1600000
#define ESMAX 30000
#define NREL  16

// ---------------- device scratch (no allocations allowed) ----------------
__device__ float g_h[(size_t)NMAX * D];    // GEMM outputs (h1, then h2)
__device__ float g_a[(size_t)NMAX * D];    // aggregation buffer (x pre-relu, then z)
__device__ float g_dinv[NMAX];             // degree, then d^-1/2 in place
__device__ int   g_cnt[NREL];
__device__ int   g_cur[NREL];
__device__ int   g_off[NREL + 1];
__device__ int   g_perm[ESMAX];

// ---------------- f32x2 packed-FMA helpers ----------------
__device__ __forceinline__ unsigned long long dup2(float a) {
    unsigned long long r;
    asm("mov.b64 %0, {%1, %1};" : "=l"(r) : "f"(a));
    return r;
}
__device__ __forceinline__ void fma2(unsigned long long& c, unsigned long long a,
                                     unsigned long long b) {
    asm("fma.rn.f32x2 %0, %1, %2, %0;" : "+l"(c) : "l"(a), "l"(b));
}
__device__ __forceinline__ float2 unpack2(unsigned long long v) {
    float2 f;
    asm("mov.b64 {%0, %1}, %2;" : "=f"(f.x), "=f"(f.y) : "l"(v));
    return f;
}

// ---------------- small prep kernels ----------------
__global__ void zero_kernel(int n) {
    int i = blockIdx.x * blockDim.x + threadIdx.x;
    if (i < n) g_dinv[i] = 0.0f;
    if (i < NREL) g_cnt[i] = 0;
}

__global__ void deg_kernel(const int* __restrict__ dst, int E) {
    int i = blockIdx.x * blockDim.x + threadIdx.x;
    if (i < E) atomicAdd(&g_dinv[dst[i]], 1.0f);
}

__global__ void dinv_kernel(int n) {
    int i = blockIdx.x * blockDim.x + threadIdx.x;
    if (i < n) {
        float d = g_dinv[i];
        g_dinv[i] = (d > 0.0f) ? (1.0f / sqrtf(d)) : 0.0f;
    }
}

// buf[n, D] = bias[D] broadcast (fuses the "+ b" of the conv)
__global__ void init_bias_kernel(float* __restrict__ buf, const float* __restrict__ bias, int total) {
    int i = blockIdx.x * blockDim.x + threadIdx.x;
    if (i < total) buf[i] = bias[i & (D - 1)];
}

// ---------------- fp32x2 GEMM: C[M,128] = op(A)[M,128] @ W[128,128] ----------------
// 128x128 output tile per 256-thread block, 8x8 microtile/thread (packed pairs
// along j), K-chunks of 32.
template <bool RELU>
__global__ __launch_bounds__(256, 2) void gemm_kernel(
    const float* __restrict__ A, const float* __restrict__ W,
    float* __restrict__ C, int M)
{
    __shared__ __align__(16) float As[32][D];   // transposed: As[k][m]
    __shared__ __align__(16) float Bs[32][D];   // Bs[k][n]
    const int tid = threadIdx.x;
    const int tx  = tid & 15;
    const int ty  = tid >> 4;
    const int base = blockIdx.x * 128;

    unsigned long long acc[8][4];
#pragma unroll
    for (int i = 0; i < 8; i++)
#pragma unroll
        for (int j = 0; j < 4; j++) acc[i][j] = 0ull;

#pragma unroll 1
    for (int kc = 0; kc < D; kc += 32) {
#pragma unroll
        for (int it = 0; it < 4; it++) {
            int idx = tid + it * 256;          // 0..1023 float4s
            int r   = idx >> 3;
            int c4  = idx & 7;
            int gr  = base + r;
            float4 v = make_float4(0.f, 0.f, 0.f, 0.f);
            if (gr < M) v = *(const float4*)(A + (size_t)gr * D + kc + c4 * 4);
            if (RELU) {
                v.x = fmaxf(v.x, 0.f); v.y = fmaxf(v.y, 0.f);
                v.z = fmaxf(v.z, 0.f); v.w = fmaxf(v.w, 0.f);
            }
            int kk = c4 * 4;
            As[kk + 0][r] = v.x; As[kk + 1][r] = v.y;
            As[kk + 2][r] = v.z; As[kk + 3][r] = v.w;
        }
#pragma unroll
        for (int it = 0; it < 4; it++) {
            int idx = tid + it * 256;
            int k   = idx >> 5;
            int c4  = idx & 31;
            *(float4*)(&Bs[k][c4 * 4]) =
                *(const float4*)(W + (size_t)(kc + k) * D + c4 * 4);
        }
        __syncthreads();

#pragma unroll 8
        for (int k = 0; k < 32; k++) {
            float a[8];
            *(float4*)&a[0] = *(const float4*)&As[k][ty * 8];
            *(float4*)&a[4] = *(const float4*)&As[k][ty * 8 + 4];
            ulonglong2 b01 = *(const ulonglong2*)&Bs[k][tx * 8];
            ulonglong2 b23 = *(const ulonglong2*)&Bs[k][tx * 8 + 4];
#pragma unroll
            for (int i = 0; i < 8; i++) {
                unsigned long long ad = dup2(a[i]);
                fma2(acc[i][0], ad, b01.x);
                fma2(acc[i][1], ad, b01.y);
                fma2(acc[i][2], ad, b23.x);
                fma2(acc[i][3], ad, b23.y);
            }
        }
        __syncthreads();
    }

#pragma unroll
    for (int i = 0; i < 8; i++) {
        int gr = base + ty * 8 + i;
        if (gr < M) {
            float2 p0 = unpack2(acc[i][0]), p1 = unpack2(acc[i][1]);
            float2 p2 = unpack2(acc[i][2]), p3 = unpack2(acc[i][3]);
            *(float4*)(C + (size_t)gr * D + tx * 8)     = make_float4(p0.x, p0.y, p1.x, p1.y);
            *(float4*)(C + (size_t)gr * D + tx * 8 + 4) = make_float4(p2.x, p2.y, p3.x, p3.y);
        }
    }
}

// ---------------- edge scatter: agg[dst] += dinv[src]*dinv[dst] * h[src] ----------------
// one warp per edge; lane handles 16B; vector reduction (sm_90+ red.v4.f32)
__global__ __launch_bounds__(256) void scatter_kernel(
    const float* __restrict__ h, const int* __restrict__ src,
    const int* __restrict__ dst, float* __restrict__ agg, int E)
{
    int gt   = blockIdx.x * blockDim.x + threadIdx.x;
    int e    = gt >> 5;
    int lane = gt & 31;
    if (e >= E) return;
    int   s = src[e];
    int   d = dst[e];
    float w = g_dinv[s] * g_dinv[d];
    float4 v = *(const float4*)(h + (size_t)s * D + lane * 4);
    v.x *= w; v.y *= w; v.z *= w; v.w *= w;
    float* p = agg + (size_t)d * D + lane * 4;
    asm volatile("red.global.add.v4.f32 [%0], {%1, %2, %3, %4};"
                 :: "l"(p), "f"(v.x), "f"(v.y), "f"(v.z), "f"(v.w) : "memory");
}

// ---------------- relation counting sort (16 bins) ----------------
__global__ void hist_kernel(const int* __restrict__ rel, int ES) {
    int i = blockIdx.x * blockDim.x + threadIdx.x;
    if (i < ES) atomicAdd(&g_cnt[rel[i]], 1);
}
__global__ void scan_kernel() {
    if (threadIdx.x == 0) {
        int s = 0;
        for (int r = 0; r < NREL; r++) { g_off[r] = s; g_cur[r] = s; s += g_cnt[r]; }
        g_off[NREL] = s;
    }
}
__global__ void perm_kernel(const int* __restrict__ rel, int ES) {
    int i = blockIdx.x * blockDim.x + threadIdx.x;
    if (i < ES) {
        int pos = atomicAdd(&g_cur[rel[i]], 1);
        g_perm[pos] = i;
    }
}

// ---------------- scoring as per-relation GEMM ----------------
// Block (bx, r): rows [g_off[r] + bx*128, ...) of the relation-sorted triple list.
// A tile = gathered z[head] rows, B = W_r, epilogue dots with z[tail] and
// reduces over the 16 tx lanes (width-16 shuffles).
__global__ __launch_bounds__(256, 2) void score_gemm_kernel(
    const float* __restrict__ z, const float* __restrict__ relW,
    const int* __restrict__ head, const int* __restrict__ tail,
    float* __restrict__ out)
{
    __shared__ __align__(16) float As[32][D];
    __shared__ __align__(16) float Bs[32][D];
    __shared__ int sHead[128], sTail[128], sIdx[128];

    const int r     = blockIdx.y;
    const int start = g_off[r];
    const int end   = g_off[r + 1];
    const int t0    = start + blockIdx.x * 128;
    if (t0 >= end) return;

    const int tid = threadIdx.x;
    const int tx  = tid & 15;
    const int ty  = tid >> 4;

    if (tid < 128) {
        int t = t0 + tid;
        if (t < end) {
            int idx = g_perm[t];
            sIdx[tid]  = idx;
            sHead[tid] = head[idx];
            sTail[tid] = tail[idx];
        } else {
            sIdx[tid] = -1; sHead[tid] = 0; sTail[tid] = 0;
        }
    }
    __syncthreads();

    const float* Wr = relW + (size_t)r * D * D;

    unsigned long long acc[8][4];
#pragma unroll
    for (int i = 0; i < 8; i++)
#pragma unroll
        for (int j = 0; j < 4; j++) acc[i][j] = 0ull;

#pragma unroll 1
    for (int kc = 0; kc < D; kc += 32) {
#pragma unroll
        for (int it = 0; it < 4; it++) {
            int idx = tid + it * 256;
            int rr  = idx >> 3;
            int c4  = idx & 7;
            float4 v = *(const float4*)(z + (size_t)sHead[rr] * D + kc + c4 * 4);
            int kk = c4 * 4;
            As[kk + 0][rr] = v.x; As[kk + 1][rr] = v.y;
            As[kk + 2][rr] = v.z; As[kk + 3][rr] = v.w;
        }
#pragma unroll
        for (int it = 0; it < 4; it++) {
            int idx = tid + it * 256;
            int k   = idx >> 5;
            int c4  = idx & 31;
            *(float4*)(&Bs[k][c4 * 4]) =
                *(const float4*)(Wr + (size_t)(kc + k) * D + c4 * 4);
        }
        __syncthreads();

#pragma unroll 8
        for (int k = 0; k < 32; k++) {
            float a[8];
            *(float4*)&a[0] = *(const float4*)&As[k][ty * 8];
            *(float4*)&a[4] = *(const float4*)&As[k][ty * 8 + 4];
            ulonglong2 b01 = *(const ulonglong2*)&Bs[k][tx * 8];
            ulonglong2 b23 = *(const ulonglong2*)&Bs[k][tx * 8 + 4];
#pragma unroll
            for (int i = 0; i < 8; i++) {
                unsigned long long ad = dup2(a[i]);
                fma2(acc[i][0], ad, b01.x);
                fma2(acc[i][1], ad, b01.y);
                fma2(acc[i][2], ad, b23.x);
                fma2(acc[i][3], ad, b23.y);
            }
        }
        __syncthreads();
    }

    // epilogue: s[row] = sum_c U[row][c] * z[tail[row]][c]
#pragma unroll
    for (int i = 0; i < 8; i++) {
        int rr   = ty * 8 + i;
        int oidx = sIdx[rr];
        int tl   = sTail[rr];
        float4 z0 = *(const float4*)(z + (size_t)tl * D + tx * 8);
        float4 z1 = *(const float4*)(z + (size_t)tl * D + tx * 8 + 4);
        float2 p0 = unpack2(acc[i][0]), p1 = unpack2(acc[i][1]);
        float2 p2 = unpack2(acc[i][2]), p3 = unpack2(acc[i][3]);
        float p = p0.x * z0.x + p0.y * z0.y + p1.x * z0.z + p1.y * z0.w
                + p2.x * z1.x + p2.y * z1.y + p3.x * z1.z + p3.y * z1.w;
#pragma unroll
        for (int o = 8; o > 0; o >>= 1)
            p += __shfl_down_sync(0xffffffffu, p, o, 16);
        if (tx == 0 && oidx >= 0) out[oidx] = p;
    }
}

// ---------------- launch ----------------
extern "C" void kernel_launch(void* const* d_in, const int* in_sizes, int n_in,
                              void* d_out, int out_size) {
    const float* x0   = (const float*)d_in[0];
    const float* W1   = (const float*)d_in[1];
    const float* b1   = (const float*)d_in[2];
    const float* W2   = (const float*)d_in[3];
    const float* b2   = (const float*)d_in[4];
    const float* relW = (const float*)d_in[5];
    const int*   edge = (const int*)  d_in[6];
    const int*   rel  = (const int*)  d_in[7];
    const int*   head = (const int*)  d_in[8];
    const int*   tail = (const int*)  d_in[9];
    float*       out  = (float*)d_out;

    const int N  = in_sizes[0] / D;
    const int E  = in_sizes[6] / 2;
    const int ES = in_sizes[7];
    const int R  = in_sizes[5] / (D * D);
    const int* src = edge;
    const int* dst = edge + E;

    float *ph = nullptr, *pa = nullptr;
    cudaGetSymbolAddress((void**)&ph, g_h);
    cudaGetSymbolAddress((void**)&pa, g_a);

    const int T = 256;
    const int ND = N * D;
    const int sc_blocks = (int)(((long long)E * 32 + T - 1) / T);

    // degrees + d^-1/2 (norm fused into scatter)
    zero_kernel<<<(N + T - 1) / T, T>>>(N);
    deg_kernel<<<(E + T - 1) / T, T>>>(dst, E);
    dinv_kernel<<<(N + T - 1) / T, T>>>(N);

    // relation counting sort (independent of layers; overlap with them)
    hist_kernel<<<(ES + T - 1) / T, T>>>(rel, ES);
    scan_kernel<<<1, 32>>>();
    perm_kernel<<<(ES + T - 1) / T, T>>>(rel, ES);

    // layer 1: h1 = x0 @ W1 ; agg1 = b1 + scatter(norm * h1[src] -> dst)
    gemm_kernel<false><<<(N + 127) / 128, 256>>>(x0, W1, ph, N);
    init_bias_kernel<<<(ND + T - 1) / T, T>>>(pa, b1, ND);
    scatter_kernel<<<sc_blocks, T>>>(ph, src, dst, pa, E);

    // layer 2: h2 = relu(agg1) @ W2 ; z = b2 + scatter(norm * h2[src] -> dst)
    gemm_kernel<true><<<(N + 127) / 128, 256>>>(pa, W2, ph, N);
    init_bias_kernel<<<(ND + T - 1) / T, T>>>(pa, b2, ND);
    scatter_kernel<<<sc_blocks, T>>>(ph, src, dst, pa, E);

    // per-relation GEMM scoring over the sorted triple list
    dim3 sgrid((ES + 127) / 128, R);
    score_gemm_kernel<<<sgrid, 256>>>(pa, relW, head, tail, out);
}

// round 8
// speedup vs baseline: 1.9849x; 1.6463x over previous
#include <cuda_runtime.h>

#define D     128
#define NMAX  100000
#define EMAX  1600000
#define ESMAX 30000
#define NREL  16
#define SCANB 1024

// ---------------- device scratch (no allocations allowed) ----------------
__device__ float g_h[(size_t)NMAX * D];    // GEMM outputs (h1, then h2)
__device__ float g_a[(size_t)NMAX * D];    // aggregation buffer (x pre-relu, then z)
__device__ float g_dinv[NMAX];             // d^-1/2
__device__ int   g_rowcnt[NMAX];           // in-degree counts
__device__ int   g_rowoff[NMAX + 1];       // CSR row offsets (by dst)
__device__ int   g_ncur[NMAX];             // atomic cursors for edge permutation
__device__ int   g_blk[(NMAX + SCANB - 1) / SCANB + 1];
__device__ int2  g_edata[EMAX];            // (src, w-bits), sorted by dst
__device__ int   g_cnt[NREL];
__device__ int   g_cur[NREL];
__device__ int   g_off[NREL + 1];
__device__ int   g_perm[ESMAX];

// ---------------- f32x2 packed-FMA helpers ----------------
__device__ __forceinline__ unsigned long long dup2(float a) {
    unsigned long long r;
    asm("mov.b64 %0, {%1, %1};" : "=l"(r) : "f"(a));
    return r;
}
__device__ __forceinline__ void fma2(unsigned long long& c, unsigned long long a,
                                     unsigned long long b) {
    asm("fma.rn.f32x2 %0, %1, %2, %0;" : "+l"(c) : "l"(a), "l"(b));
}
__device__ __forceinline__ float2 unpack2(unsigned long long v) {
    float2 f;
    asm("mov.b64 {%0, %1}, %2;" : "=f"(f.x), "=f"(f.y) : "l"(v));
    return f;
}

// ---------------- prep: degrees, scan (CSR), edge permutation ----------------
__global__ void zero_kernel(int n) {
    int i = blockIdx.x * blockDim.x + threadIdx.x;
    if (i < n) g_rowcnt[i] = 0;
    if (i < NREL) g_cnt[i] = 0;
}

__global__ void deg_kernel(const int* __restrict__ dst, int E) {
    int i = blockIdx.x * blockDim.x + threadIdx.x;
    if (i < E) atomicAdd(&g_rowcnt[dst[i]], 1);
}

// per-block exclusive scan of counts; fuses dinv computation
__global__ __launch_bounds__(SCANB) void scan1_kernel(int N) {
    __shared__ int s[SCANB];
    int t = threadIdx.x;
    int i = blockIdx.x * SCANB + t;
    int v = (i < N) ? g_rowcnt[i] : 0;
    s[t] = v;
    __syncthreads();
#pragma unroll
    for (int off = 1; off < SCANB; off <<= 1) {
        int add = (t >= off) ? s[t - off] : 0;
        __syncthreads();
        s[t] += add;
        __syncthreads();
    }
    if (i < N) {
        g_rowoff[i] = s[t] - v;                       // block-local exclusive
        g_dinv[i]   = (v > 0) ? rsqrtf((float)v) : 0.0f;
    }
    if (t == SCANB - 1) g_blk[blockIdx.x] = s[t];
}

__global__ void scan2_kernel(int nb, int N, int E) {
    __shared__ int s[256];
    int t = threadIdx.x;
    if (t < nb) s[t] = g_blk[t];
    __syncthreads();
    if (t == 0) {
        int a = 0;
        for (int b = 0; b < nb; b++) { int v = s[b]; s[b] = a; a += v; }
        g_rowoff[N] = E;
    }
    __syncthreads();
    if (t < nb) g_blk[t] = s[t];
}

__global__ void scan3_kernel(int N) {
    int i = blockIdx.x * blockDim.x + threadIdx.x;
    if (i < N) {
        int o = g_rowoff[i] + g_blk[i >> 10];
        g_rowoff[i] = o;
        g_ncur[i]   = o;
    }
}

// group edges by dst; pack (src, norm-weight) per edge
__global__ void eperm_kernel(const int* __restrict__ src, const int* __restrict__ dst, int E) {
    int e = blockIdx.x * blockDim.x + threadIdx.x;
    if (e < E) {
        int s = src[e], d = dst[e];
        int pos = atomicAdd(&g_ncur[d], 1);
        float w = g_dinv[s] * g_dinv[d];
        g_edata[pos] = make_int2(s, __float_as_int(w));
    }
}

// ---------------- fp32x2 GEMM: C[M,128] = op(A)[M,128] @ W[128,128] ----------------
template <bool RELU>
__global__ __launch_bounds__(256, 2) void gemm_kernel(
    const float* __restrict__ A, const float* __restrict__ W,
    float* __restrict__ C, int M)
{
    __shared__ __align__(16) float As[32][D];   // transposed: As[k][m]
    __shared__ __align__(16) float Bs[32][D];   // Bs[k][n]
    const int tid = threadIdx.x;
    const int tx  = tid & 15;
    const int ty  = tid >> 4;
    const int base = blockIdx.x * 128;

    unsigned long long acc[8][4];
#pragma unroll
    for (int i = 0; i < 8; i++)
#pragma unroll
        for (int j = 0; j < 4; j++) acc[i][j] = 0ull;

#pragma unroll 1
    for (int kc = 0; kc < D; kc += 32) {
#pragma unroll
        for (int it = 0; it < 4; it++) {
            int idx = tid + it * 256;
            int r   = idx >> 3;
            int c4  = idx & 7;
            int gr  = base + r;
            float4 v = make_float4(0.f, 0.f, 0.f, 0.f);
            if (gr < M) v = *(const float4*)(A + (size_t)gr * D + kc + c4 * 4);
            if (RELU) {
                v.x = fmaxf(v.x, 0.f); v.y = fmaxf(v.y, 0.f);
                v.z = fmaxf(v.z, 0.f); v.w = fmaxf(v.w, 0.f);
            }
            int kk = c4 * 4;
            As[kk + 0][r] = v.x; As[kk + 1][r] = v.y;
            As[kk + 2][r] = v.z; As[kk + 3][r] = v.w;
        }
#pragma unroll
        for (int it = 0; it < 4; it++) {
            int idx = tid + it * 256;
            int k   = idx >> 5;
            int c4  = idx & 31;
            *(float4*)(&Bs[k][c4 * 4]) =
                *(const float4*)(W + (size_t)(kc + k) * D + c4 * 4);
        }
        __syncthreads();

#pragma unroll 8
        for (int k = 0; k < 32; k++) {
            float a[8];
            *(float4*)&a[0] = *(const float4*)&As[k][ty * 8];
            *(float4*)&a[4] = *(const float4*)&As[k][ty * 8 + 4];
            ulonglong2 b01 = *(const ulonglong2*)&Bs[k][tx * 8];
            ulonglong2 b23 = *(const ulonglong2*)&Bs[k][tx * 8 + 4];
#pragma unroll
            for (int i = 0; i < 8; i++) {
                unsigned long long ad = dup2(a[i]);
                fma2(acc[i][0], ad, b01.x);
                fma2(acc[i][1], ad, b01.y);
                fma2(acc[i][2], ad, b23.x);
                fma2(acc[i][3], ad, b23.y);
            }
        }
        __syncthreads();
    }

#pragma unroll
    for (int i = 0; i < 8; i++) {
        int gr = base + ty * 8 + i;
        if (gr < M) {
            float2 p0 = unpack2(acc[i][0]), p1 = unpack2(acc[i][1]);
            float2 p2 = unpack2(acc[i][2]), p3 = unpack2(acc[i][3]);
            *(float4*)(C + (size_t)gr * D + tx * 8)     = make_float4(p0.x, p0.y, p1.x, p1.y);
            *(float4*)(C + (size_t)gr * D + tx * 8 + 4) = make_float4(p2.x, p2.y, p3.x, p3.y);
        }
    }
}

// ---------------- CSR aggregation: agg[n] = b + sum_{e in row n} w_e * h[src_e] ----------------
// one warp per node; lane handles 16B; atomic-free.
__global__ __launch_bounds__(256) void agg_kernel(
    const float* __restrict__ h, const float* __restrict__ bias,
    float* __restrict__ outb, int N)
{
    int gt   = blockIdx.x * blockDim.x + threadIdx.x;
    int node = gt >> 5;
    int lane = gt & 31;
    if (node >= N) return;

    int e  = g_rowoff[node];
    int e1 = g_rowoff[node + 1];
    float4 acc = *(const float4*)(bias + lane * 4);

    // 2-deep pipeline for load MLP
    for (; e + 1 < e1; e += 2) {
        int2 d0 = g_edata[e];
        int2 d1 = g_edata[e + 1];
        float4 v0 = *(const float4*)(h + (size_t)d0.x * D + lane * 4);
        float4 v1 = *(const float4*)(h + (size_t)d1.x * D + lane * 4);
        float w0 = __int_as_float(d0.y);
        float w1 = __int_as_float(d1.y);
        acc.x = fmaf(w0, v0.x, acc.x); acc.y = fmaf(w0, v0.y, acc.y);
        acc.z = fmaf(w0, v0.z, acc.z); acc.w = fmaf(w0, v0.w, acc.w);
        acc.x = fmaf(w1, v1.x, acc.x); acc.y = fmaf(w1, v1.y, acc.y);
        acc.z = fmaf(w1, v1.z, acc.z); acc.w = fmaf(w1, v1.w, acc.w);
    }
    if (e < e1) {
        int2 d0 = g_edata[e];
        float4 v0 = *(const float4*)(h + (size_t)d0.x * D + lane * 4);
        float w0 = __int_as_float(d0.y);
        acc.x = fmaf(w0, v0.x, acc.x); acc.y = fmaf(w0, v0.y, acc.y);
        acc.z = fmaf(w0, v0.z, acc.z); acc.w = fmaf(w0, v0.w, acc.w);
    }
    *(float4*)(outb + (size_t)node * D + lane * 4) = acc;
}

// ---------------- relation counting sort (16 bins) ----------------
__global__ void hist_kernel(const int* __restrict__ rel, int ES) {
    int i = blockIdx.x * blockDim.x + threadIdx.x;
    if (i < ES) atomicAdd(&g_cnt[rel[i]], 1);
}
__global__ void rscan_kernel() {
    if (threadIdx.x == 0) {
        int s = 0;
        for (int r = 0; r < NREL; r++) { g_off[r] = s; g_cur[r] = s; s += g_cnt[r]; }
        g_off[NREL] = s;
    }
}
__global__ void rperm_kernel(const int* __restrict__ rel, int ES) {
    int i = blockIdx.x * blockDim.x + threadIdx.x;
    if (i < ES) {
        int pos = atomicAdd(&g_cur[rel[i]], 1);
        g_perm[pos] = i;
    }
}

// ---------------- scoring as per-relation GEMM ----------------
__global__ __launch_bounds__(256, 2) void score_gemm_kernel(
    const float* __restrict__ z, const float* __restrict__ relW,
    const int* __restrict__ head, const int* __restrict__ tail,
    float* __restrict__ out)
{
    __shared__ __align__(16) float As[32][D];
    __shared__ __align__(16) float Bs[32][D];
    __shared__ int sHead[128], sTail[128], sIdx[128];

    const int r     = blockIdx.y;
    const int start = g_off[r];
    const int end   = g_off[r + 1];
    const int t0    = start + blockIdx.x * 128;
    if (t0 >= end) return;

    const int tid = threadIdx.x;
    const int tx  = tid & 15;
    const int ty  = tid >> 4;

    if (tid < 128) {
        int t = t0 + tid;
        if (t < end) {
            int idx = g_perm[t];
            sIdx[tid]  = idx;
            sHead[tid] = head[idx];
            sTail[tid] = tail[idx];
        } else {
            sIdx[tid] = -1; sHead[tid] = 0; sTail[tid] = 0;
        }
    }
    __syncthreads();

    const float* Wr = relW + (size_t)r * D * D;

    unsigned long long acc[8][4];
#pragma unroll
    for (int i = 0; i < 8; i++)
#pragma unroll
        for (int j = 0; j < 4; j++) acc[i][j] = 0ull;

#pragma unroll 1
    for (int kc = 0; kc < D; kc += 32) {
#pragma unroll
        for (int it = 0; it < 4; it++) {
            int idx = tid + it * 256;
            int rr  = idx >> 3;
            int c4  = idx & 7;
            float4 v = *(const float4*)(z + (size_t)sHead[rr] * D + kc + c4 * 4);
            int kk = c4 * 4;
            As[kk + 0][rr] = v.x; As[kk + 1][rr] = v.y;
            As[kk + 2][rr] = v.z; As[kk + 3][rr] = v.w;
        }
#pragma unroll
        for (int it = 0; it < 4; it++) {
            int idx = tid + it * 256;
            int k   = idx >> 5;
            int c4  = idx & 31;
            *(float4*)(&Bs[k][c4 * 4]) =
                *(const float4*)(Wr + (size_t)(kc + k) * D + c4 * 4);
        }
        __syncthreads();

#pragma unroll 8
        for (int k = 0; k < 32; k++) {
            float a[8];
            *(float4*)&a[0] = *(const float4*)&As[k][ty * 8];
            *(float4*)&a[4] = *(const float4*)&As[k][ty * 8 + 4];
            ulonglong2 b01 = *(const ulonglong2*)&Bs[k][tx * 8];
            ulonglong2 b23 = *(const ulonglong2*)&Bs[k][tx * 8 + 4];
#pragma unroll
            for (int i = 0; i < 8; i++) {
                unsigned long long ad = dup2(a[i]);
                fma2(acc[i][0], ad, b01.x);
                fma2(acc[i][1], ad, b01.y);
                fma2(acc[i][2], ad, b23.x);
                fma2(acc[i][3], ad, b23.y);
            }
        }
        __syncthreads();
    }

    // epilogue: s[row] = sum_c U[row][c] * z[tail[row]][c]
#pragma unroll
    for (int i = 0; i < 8; i++) {
        int rr   = ty * 8 + i;
        int oidx = sIdx[rr];
        int tl   = sTail[rr];
        float4 z0 = *(const float4*)(z + (size_t)tl * D + tx * 8);
        float4 z1 = *(const float4*)(z + (size_t)tl * D + tx * 8 + 4);
        float2 p0 = unpack2(acc[i][0]), p1 = unpack2(acc[i][1]);
        float2 p2 = unpack2(acc[i][2]), p3 = unpack2(acc[i][3]);
        float p = p0.x * z0.x + p0.y * z0.y + p1.x * z0.z + p1.y * z0.w
                + p2.x * z1.x + p2.y * z1.y + p3.x * z1.z + p3.y * z1.w;
#pragma unroll
        for (int o = 8; o > 0; o >>= 1)
            p += __shfl_down_sync(0xffffffffu, p, o, 16);
        if (tx == 0 && oidx >= 0) out[oidx] = p;
    }
}

// ---------------- launch ----------------
extern "C" void kernel_launch(void* const* d_in, const int* in_sizes, int n_in,
                              void* d_out, int out_size) {
    const float* x0   = (const float*)d_in[0];
    const float* W1   = (const float*)d_in[1];
    const float* b1   = (const float*)d_in[2];
    const float* W2   = (const float*)d_in[3];
    const float* b2   = (const float*)d_in[4];
    const float* relW = (const float*)d_in[5];
    const int*   edge = (const int*)  d_in[6];
    const int*   rel  = (const int*)  d_in[7];
    const int*   head = (const int*)  d_in[8];
    const int*   tail = (const int*)  d_in[9];
    float*       out  = (float*)d_out;

    const int N  = in_sizes[0] / D;
    const int E  = in_sizes[6] / 2;
    const int ES = in_sizes[7];
    const int R  = in_sizes[5] / (D * D);
    const int* src = edge;
    const int* dst = edge + E;

    float *ph = nullptr, *pa = nullptr;
    cudaGetSymbolAddress((void**)&ph, g_h);
    cudaGetSymbolAddress((void**)&pa, g_a);

    const int T = 256;
    const int nb = (N + SCANB - 1) / SCANB;
    const int agg_blocks = (int)(((long long)N * 32 + T - 1) / T);

    // CSR build (shared by both layers): degrees -> scan (+dinv) -> edge perm
    zero_kernel<<<(N + T - 1) / T, T>>>(N);
    deg_kernel<<<(E + T - 1) / T, T>>>(dst, E);
    scan1_kernel<<<nb, SCANB>>>(N);
    scan2_kernel<<<1, 256>>>(nb, N, E);
    scan3_kernel<<<(N + T - 1) / T, T>>>(N);
    eperm_kernel<<<(E + T - 1) / T, T>>>(src, dst, E);

    // relation counting sort (independent)
    hist_kernel<<<(ES + T - 1) / T, T>>>(rel, ES);
    rscan_kernel<<<1, 32>>>();
    rperm_kernel<<<(ES + T - 1) / T, T>>>(rel, ES);

    // layer 1: h1 = x0 @ W1 ; agg1 = b1 + CSR-aggregate(h1)
    gemm_kernel<false><<<(N + 127) / 128, 256>>>(x0, W1, ph, N);
    agg_kernel<<<agg_blocks, T>>>(ph, b1, pa, N);

    // layer 2: h2 = relu(agg1) @ W2 ; z = b2 + CSR-aggregate(h2)
    gemm_kernel<true><<<(N + 127) / 128, 256>>>(pa, W2, ph, N);
    agg_kernel<<<agg_blocks, T>>>(ph, b2, pa, N);

    // per-relation GEMM scoring over the sorted triple list
    dim3 sgrid((ES + 127) / 128, R);
    score_gemm_kernel<<<sgrid, 256>>>(pa, relW, head, tail, out);
}

// round 10
// speedup vs baseline: 2.1667x; 1.0916x over previous
#include <cuda_runtime.h>

#define D     128
#define NMAX  100000
#define EMAX  1600000
#define ESMAX 30000
#define NREL  16

// ---------------- device scratch (no allocations allowed) ----------------
__device__ float g_h[(size_t)NMAX * D];    // GEMM outputs (h1, then h2)
__device__ float g_a[(size_t)NMAX * D];    // aggregation buffer (x pre-relu, then z)
__device__ float g_dinv[NMAX];             // d^-1/2
__device__ int   g_rowcnt[NMAX];           // in-degree counts
__device__ int   g_rowoff[NMAX + 1];       // CSR row offsets (by dst)
__device__ int   g_ncur[NMAX];             // atomic cursors for edge permutation
__device__ int2  g_edata[EMAX];            // (src, w-bits), sorted by dst
__device__ int   g_off[NREL + 1];
__device__ int   g_perm[ESMAX];
__device__ int   g_chain_flag;
__device__ int   g_chain_sum;

// ---------------- f32x2 packed-FMA helpers ----------------
__device__ __forceinline__ unsigned long long dup2(float a) {
    unsigned long long r;
    asm("mov.b64 %0, {%1, %1};" : "=l"(r) : "f"(a));
    return r;
}
__device__ __forceinline__ void fma2(unsigned long long& c, unsigned long long a,
                                     unsigned long long b) {
    asm("fma.rn.f32x2 %0, %1, %2, %0;" : "+l"(c) : "l"(a), "l"(b));
}
__device__ __forceinline__ float2 unpack2(unsigned long long v) {
    float2 f;
    asm("mov.b64 {%0, %1}, %2;" : "=f"(f.x), "=f"(f.y) : "l"(v));
    return f;
}

// ---------------- prep: degrees, chained scan (CSR), edge permutation ----------------
__global__ void zero_kernel(int n) {
    int i = blockIdx.x * blockDim.x + threadIdx.x;
    if (i < n) g_rowcnt[i] = 0;
    if (i == 0) { g_chain_flag = 0; g_chain_sum = 0; }
}

__global__ void deg_kernel(const int* __restrict__ dst, int E) {
    int i = blockIdx.x * blockDim.x + threadIdx.x;
    if (i < E) atomicAdd(&g_rowcnt[dst[i]], 1);
}

// single-kernel chained-lookback exclusive scan; fuses dinv + cursor init.
// 8192 items/block; all blocks co-resident (<= 13 blocks), so the spin is safe.
__global__ __launch_bounds__(1024) void scan_kernel(int N, int E) {
    __shared__ int wsum[32];
    __shared__ int wpre[32];
    __shared__ int s_base;
    const int t = threadIdx.x, b = blockIdx.x;
    const int lane = t & 31, wid = t >> 5;
    const int idx0 = b * 8192 + t * 8;

    int v[8]; int tsum = 0;
#pragma unroll
    for (int i = 0; i < 8; i++) {
        int ii = idx0 + i;
        v[i] = (ii < N) ? g_rowcnt[ii] : 0;
        tsum += v[i];
    }
    int inc = tsum;
#pragma unroll
    for (int o = 1; o < 32; o <<= 1) {
        int x = __shfl_up_sync(~0u, inc, o);
        if (lane >= o) inc += x;
    }
    if (lane == 31) wsum[wid] = inc;
    __syncthreads();
    if (wid == 0) {
        int xi = wsum[lane];
#pragma unroll
        for (int o = 1; o < 32; o <<= 1) {
            int y = __shfl_up_sync(~0u, xi, o);
            if (lane >= o) xi += y;
        }
        wpre[lane] = xi;
    }
    __syncthreads();
    const int block_total = wpre[31];
    const int thread_excl = inc - tsum + (wid > 0 ? wpre[wid - 1] : 0);

    if (t == 0) {
        while (*(volatile int*)&g_chain_flag != b) { }
        int base = g_chain_sum;
        s_base = base;
        g_chain_sum = base + block_total;
        __threadfence();
        *(volatile int*)&g_chain_flag = b + 1;
    }
    __syncthreads();

    int run = s_base + thread_excl;
#pragma unroll
    for (int i = 0; i < 8; i++) {
        int ii = idx0 + i;
        if (ii < N) {
            g_rowoff[ii] = run;
            g_ncur[ii]   = run;
            g_dinv[ii]   = (v[i] > 0) ? rsqrtf((float)v[i]) : 0.0f;
        }
        run += v[i];
    }
    if (b == 0 && t == 0) g_rowoff[N] = E;
}

// group edges by dst; pack (src, norm-weight) per edge
__global__ void eperm_kernel(const int* __restrict__ src, const int* __restrict__ dst, int E) {
    int e = blockIdx.x * blockDim.x + threadIdx.x;
    if (e < E) {
        int s = src[e], d = dst[e];
        int pos = atomicAdd(&g_ncur[d], 1);
        float w = g_dinv[s] * g_dinv[d];
        g_edata[pos] = make_int2(s, __float_as_int(w));
    }
}

// ---------------- fused relation counting sort (single block) ----------------
__global__ __launch_bounds__(1024) void relsort_kernel(const int* __restrict__ rel, int ES) {
    __shared__ int hist[NREL];
    const int t = threadIdx.x;
    if (t < NREL) hist[t] = 0;
    __syncthreads();
    for (int i = t; i < ES; i += 1024) atomicAdd(&hist[rel[i]], 1);
    __syncthreads();
    if (t == 0) {
        int s = 0;
        for (int r = 0; r < NREL; r++) { g_off[r] = s; int c = hist[r]; hist[r] = s; s += c; }
        g_off[NREL] = s;
    }
    __syncthreads();
    for (int i = t; i < ES; i += 1024) {
        int pos = atomicAdd(&hist[rel[i]], 1);
        g_perm[pos] = i;
    }
}

// ---------------- fp32x2 GEMM: C[M,128] = op(A)[M,128] @ W[128,128] ----------------
template <bool RELU>
__global__ __launch_bounds__(256, 2) void gemm_kernel(
    const float* __restrict__ A, const float* __restrict__ W,
    float* __restrict__ C, int M)
{
    __shared__ __align__(16) float As[32][D];   // transposed: As[k][m]
    __shared__ __align__(16) float Bs[32][D];   // Bs[k][n]
    const int tid = threadIdx.x;
    const int tx  = tid & 15;
    const int ty  = tid >> 4;
    const int base = blockIdx.x * 128;

    unsigned long long acc[8][4];
#pragma unroll
    for (int i = 0; i < 8; i++)
#pragma unroll
        for (int j = 0; j < 4; j++) acc[i][j] = 0ull;

#pragma unroll 1
    for (int kc = 0; kc < D; kc += 32) {
#pragma unroll
        for (int it = 0; it < 4; it++) {
            int idx = tid + it * 256;
            int r   = idx >> 3;
            int c4  = idx & 7;
            int gr  = base + r;
            float4 v = make_float4(0.f, 0.f, 0.f, 0.f);
            if (gr < M) v = *(const float4*)(A + (size_t)gr * D + kc + c4 * 4);
            if (RELU) {
                v.x = fmaxf(v.x, 0.f); v.y = fmaxf(v.y, 0.f);
                v.z = fmaxf(v.z, 0.f); v.w = fmaxf(v.w, 0.f);
            }
            int kk = c4 * 4;
            As[kk + 0][r] = v.x; As[kk + 1][r] = v.y;
            As[kk + 2][r] = v.z; As[kk + 3][r] = v.w;
        }
#pragma unroll
        for (int it = 0; it < 4; it++) {
            int idx = tid + it * 256;
            int k   = idx >> 5;
            int c4  = idx & 31;
            *(float4*)(&Bs[k][c4 * 4]) =
                *(const float4*)(W + (size_t)(kc + k) * D + c4 * 4);
        }
        __syncthreads();

#pragma unroll 8
        for (int k = 0; k < 32; k++) {
            float a[8];
            *(float4*)&a[0] = *(const float4*)&As[k][ty * 8];
            *(float4*)&a[4] = *(const float4*)&As[k][ty * 8 + 4];
            ulonglong2 b01 = *(const ulonglong2*)&Bs[k][tx * 8];
            ulonglong2 b23 = *(const ulonglong2*)&Bs[k][tx * 8 + 4];
#pragma unroll
            for (int i = 0; i < 8; i++) {
                unsigned long long ad = dup2(a[i]);
                fma2(acc[i][0], ad, b01.x);
                fma2(acc[i][1], ad, b01.y);
                fma2(acc[i][2], ad, b23.x);
                fma2(acc[i][3], ad, b23.y);
            }
        }
        __syncthreads();
    }

#pragma unroll
    for (int i = 0; i < 8; i++) {
        int gr = base + ty * 8 + i;
        if (gr < M) {
            float2 p0 = unpack2(acc[i][0]), p1 = unpack2(acc[i][1]);
            float2 p2 = unpack2(acc[i][2]), p3 = unpack2(acc[i][3]);
            *(float4*)(C + (size_t)gr * D + tx * 8)     = make_float4(p0.x, p0.y, p1.x, p1.y);
            *(float4*)(C + (size_t)gr * D + tx * 8 + 4) = make_float4(p2.x, p2.y, p3.x, p3.y);
        }
    }
}

// ---------------- CSR aggregation: agg[n] = b + sum_{e in row n} w_e * h[src_e] ----------------
// one warp per node; lane handles 16B; atomic-free; 4-deep load pipeline.
__global__ __launch_bounds__(256) void agg_kernel(
    const float* __restrict__ h, const float* __restrict__ bias,
    float* __restrict__ outb, int N)
{
    int gt   = blockIdx.x * blockDim.x + threadIdx.x;
    int node = gt >> 5;
    int lane = gt & 31;
    if (node >= N) return;

    int e  = g_rowoff[node];
    int e1 = g_rowoff[node + 1];
    float4 acc = *(const float4*)(bias + lane * 4);

    for (; e + 4 <= e1; e += 4) {
        int2 d0 = g_edata[e];
        int2 d1 = g_edata[e + 1];
        int2 d2 = g_edata[e + 2];
        int2 d3 = g_edata[e + 3];
        float4 v0 = *(const float4*)(h + (size_t)d0.x * D + lane * 4);
        float4 v1 = *(const float4*)(h + (size_t)d1.x * D + lane * 4);
        float4 v2 = *(const float4*)(h + (size_t)d2.x * D + lane * 4);
        float4 v3 = *(const float4*)(h + (size_t)d3.x * D + lane * 4);
        float w0 = __int_as_float(d0.y), w1 = __int_as_float(d1.y);
        float w2 = __int_as_float(d2.y), w3 = __int_as_float(d3.y);
        acc.x = fmaf(w0, v0.x, acc.x); acc.y = fmaf(w0, v0.y, acc.y);
        acc.z = fmaf(w0, v0.z, acc.z); acc.w = fmaf(w0, v0.w, acc.w);
        acc.x = fmaf(w1, v1.x, acc.x); acc.y = fmaf(w1, v1.y, acc.y);
        acc.z = fmaf(w1, v1.z, acc.z); acc.w = fmaf(w1, v1.w, acc.w);
        acc.x = fmaf(w2, v2.x, acc.x); acc.y = fmaf(w2, v2.y, acc.y);
        acc.z = fmaf(w2, v2.z, acc.z); acc.w = fmaf(w2, v2.w, acc.w);
        acc.x = fmaf(w3, v3.x, acc.x); acc.y = fmaf(w3, v3.y, acc.y);
        acc.z = fmaf(w3, v3.z, acc.z); acc.w = fmaf(w3, v3.w, acc.w);
    }
    for (; e < e1; e++) {
        int2 d0 = g_edata[e];
        float4 v0 = *(const float4*)(h + (size_t)d0.x * D + lane * 4);
        float w0 = __int_as_float(d0.y);
        acc.x = fmaf(w0, v0.x, acc.x); acc.y = fmaf(w0, v0.y, acc.y);
        acc.z = fmaf(w0, v0.z, acc.z); acc.w = fmaf(w0, v0.w, acc.w);
    }
    *(float4*)(outb + (size_t)node * D + lane * 4) = acc;
}

// ---------------- scoring as per-relation GEMM ----------------
__global__ __launch_bounds__(256, 2) void score_gemm_kernel(
    const float* __restrict__ z, const float* __restrict__ relW,
    const int* __restrict__ head, const int* __restrict__ tail,
    float* __restrict__ out)
{
    __shared__ __align__(16) float As[32][D];
    __shared__ __align__(16) float Bs[32][D];
    __shared__ int sHead[128], sTail[128], sIdx[128];

    const int r     = blockIdx.y;
    const int start = g_off[r];
    const int end   = g_off[r + 1];
    const int t0    = start + blockIdx.x * 128;
    if (t0 >= end) return;

    const int tid = threadIdx.x;
    const int tx  = tid & 15;
    const int ty  = tid >> 4;

    if (tid < 128) {
        int t = t0 + tid;
        if (t < end) {
            int idx = g_perm[t];
            sIdx[tid]  = idx;
            sHead[tid] = head[idx];
            sTail[tid] = tail[idx];
        } else {
            sIdx[tid] = -1; sHead[tid] = 0; sTail[tid] = 0;
        }
    }
    __syncthreads();

    const float* Wr = relW + (size_t)r * D * D;

    unsigned long long acc[8][4];
#pragma unroll
    for (int i = 0; i < 8; i++)
#pragma unroll
        for (int j = 0; j < 4; j++) acc[i][j] = 0ull;

#pragma unroll 1
    for (int kc = 0; kc < D; kc += 32) {
#pragma unroll
        for (int it = 0; it < 4; it++) {
            int idx = tid + it * 256;
            int rr  = idx >> 3;
            int c4  = idx & 7;
            float4 v = *(const float4*)(z + (size_t)sHead[rr] * D + kc + c4 * 4);
            int kk = c4 * 4;
            As[kk + 0][rr] = v.x; As[kk + 1][rr] = v.y;
            As[kk + 2][rr] = v.z; As[kk + 3][rr] = v.w;
        }
#pragma unroll
        for (int it = 0; it < 4; it++) {
            int idx = tid + it * 256;
            int k   = idx >> 5;
            int c4  = idx & 31;
            *(float4*)(&Bs[k][c4 * 4]) =
                *(const float4*)(Wr + (size_t)(kc + k) * D + c4 * 4);
        }
        __syncthreads();

#pragma unroll 8
        for (int k = 0; k < 32; k++) {
            float a[8];
            *(float4*)&a[0] = *(const float4*)&As[k][ty * 8];
            *(float4*)&a[4] = *(const float4*)&As[k][ty * 8 + 4];
            ulonglong2 b01 = *(const ulonglong2*)&Bs[k][tx * 8];
            ulonglong2 b23 = *(const ulonglong2*)&Bs[k][tx * 8 + 4];
#pragma unroll
            for (int i = 0; i < 8; i++) {
                unsigned long long ad = dup2(a[i]);
                fma2(acc[i][0], ad, b01.x);
                fma2(acc[i][1], ad, b01.y);
                fma2(acc[i][2], ad, b23.x);
                fma2(acc[i][3], ad, b23.y);
            }
        }
        __syncthreads();
    }

#pragma unroll
    for (int i = 0; i < 8; i++) {
        int rr   = ty * 8 + i;
        int oidx = sIdx[rr];
        int tl   = sTail[rr];
        float4 z0 = *(const float4*)(z + (size_t)tl * D + tx * 8);
        float4 z1 = *(const float4*)(z + (size_t)tl * D + tx * 8 + 4);
        float2 p0 = unpack2(acc[i][0]), p1 = unpack2(acc[i][1]);
        float2 p2 = unpack2(acc[i][2]), p3 = unpack2(acc[i][3]);
        float p = p0.x * z0.x + p0.y * z0.y + p1.x * z0.z + p1.y * z0.w
                + p2.x * z1.x + p2.y * z1.y + p3.x * z1.z + p3.y * z1.w;
#pragma unroll
        for (int o = 8; o > 0; o >>= 1)
            p += __shfl_down_sync(0xffffffffu, p, o, 16);
        if (tx == 0 && oidx >= 0) out[oidx] = p;
    }
}

// ---------------- launch ----------------
extern "C" void kernel_launch(void* const* d_in, const int* in_sizes, int n_in,
                              void* d_out, int out_size) {
    const float* x0   = (const float*)d_in[0];
    const float* W1   = (const float*)d_in[1];
    const float* b1   = (const float*)d_in[2];
    const float* W2   = (const float*)d_in[3];
    const float* b2   = (const float*)d_in[4];
    const float* relW = (const float*)d_in[5];
    const int*   edge = (const int*)  d_in[6];
    const int*   rel  = (const int*)  d_in[7];
    const int*   head = (const int*)  d_in[8];
    const int*   tail = (const int*)  d_in[9];
    float*       out  = (float*)d_out;

    const int N  = in_sizes[0] / D;
    const int E  = in_sizes[6] / 2;
    const int ES = in_sizes[7];
    const int R  = in_sizes[5] / (D * D);
    const int* src = edge;
    const int* dst = edge + E;

    float *ph = nullptr, *pa = nullptr;
    cudaGetSymbolAddress((void**)&ph, g_h);
    cudaGetSymbolAddress((void**)&pa, g_a);

    const int T = 256;
    const int scan_blocks = (N + 8191) / 8192;
    const int agg_blocks  = (int)(((long long)N * 32 + T - 1) / T);

    // lazily create a side stream + events (host resources only; created on the
    // pre-capture correctness call, reused during capture). Fallback: serial.
    static cudaStream_t s_side = nullptr;
    static cudaEvent_t  ev_fork = nullptr, ev_csr = nullptr, ev_rel = nullptr;
    static bool tried = false;
    if (!tried) {
        tried = true;
        bool ok = (cudaStreamCreateWithFlags(&s_side, cudaStreamNonBlocking) == cudaSuccess)
               && (cudaEventCreateWithFlags(&ev_fork, cudaEventDisableTiming) == cudaSuccess)
               && (cudaEventCreateWithFlags(&ev_csr,  cudaEventDisableTiming) == cudaSuccess)
               && (cudaEventCreateWithFlags(&ev_rel,  cudaEventDisableTiming) == cudaSuccess);
        if (!ok) s_side = nullptr;
    }

    if (s_side) {
        // fork: CSR build + relation sort on side stream, gemm1 on main stream
        cudaEventRecord(ev_fork, 0);
        cudaStreamWaitEvent(s_side, ev_fork, 0);

        zero_kernel<<<(N + T - 1) / T, T, 0, s_side>>>(N);
        deg_kernel<<<(E + T - 1) / T, T, 0, s_side>>>(dst, E);
        scan_kernel<<<scan_blocks, 1024, 0, s_side>>>(N, E);
        eperm_kernel<<<(E + T - 1) / T, T, 0, s_side>>>(src, dst, E);
        cudaEventRecord(ev_csr, s_side);
        relsort_kernel<<<1, 1024, 0, s_side>>>(rel, ES);
        cudaEventRecord(ev_rel, s_side);

        gemm_kernel<false><<<(N + 127) / 128, 256>>>(x0, W1, ph, N);

        cudaStreamWaitEvent(0, ev_csr, 0);
        agg_kernel<<<agg_blocks, T>>>(ph, b1, pa, N);
        gemm_kernel<true><<<(N + 127) / 128, 256>>>(pa, W2, ph, N);
        agg_kernel<<<agg_blocks, T>>>(ph, b2, pa, N);

        cudaStreamWaitEvent(0, ev_rel, 0);
        dim3 sgrid((ES + 127) / 128, R);
        score_gemm_kernel<<<sgrid, 256>>>(pa, relW, head, tail, out);
    } else {
        // serial fallback
        zero_kernel<<<(N + T - 1) / T, T>>>(N);
        deg_kernel<<<(E + T - 1) / T, T>>>(dst, E);
        scan_kernel<<<scan_blocks, 1024>>>(N, E);
        eperm_kernel<<<(E + T - 1) / T, T>>>(src, dst, E);
        relsort_kernel<<<1, 1024>>>(rel, ES);
        gemm_kernel<false><<<(N + 127) / 128, 256>>>(x0, W1, ph, N);
        agg_kernel<<<agg_blocks, T>>>(ph, b1, pa, N);
        gemm_kernel<true><<<(N + 127) / 128, 256>>>(pa, W2, ph, N);
        agg_kernel<<<agg_blocks, T>>>(ph, b2, pa, N);
        dim3 sgrid((ES + 127) / 128, R);
        score_gemm_kernel<<<sgrid, 256>>>(pa, relW, head, tail, out);
    }
}

// round 11
// speedup vs baseline: 2.3788x; 1.0979x over previous
#include <cuda_runtime.h>

#define D     128
#define NMAX  100000
#define EMAX  1600000
#define ESMAX 30000
#define NREL  16

// ---------------- device scratch (no allocations allowed) ----------------
__device__ float g_h[(size_t)NMAX * D];    // gemm1 out h1; later t2 = Agg(relu(a1))
__device__ float g_a[(size_t)NMAX * D];    // a1 = b1 + Agg(h1)
__device__ float g_dinv[NMAX];             // d^-1/2
__device__ int   g_rowcnt[NMAX];           // in-degree counts
__device__ int   g_rowoff[NMAX + 1];       // CSR row offsets (by dst)
__device__ int   g_ncur[NMAX];             // atomic cursors for edge permutation
__device__ int2  g_edata[EMAX];            // (src, w-bits), sorted by dst
__device__ int   g_off[NREL + 1];
__device__ int   g_perm[ESMAX];
__device__ int   g_chain[2];               // {flag, running sum} for chained scan
// score factorization scratch
__device__ float g_T1[(size_t)NREL * D * D];   // W_r @ W2^T
__device__ float g_M [(size_t)NREL * D * D];   // W2 @ W_r @ W2^T
__device__ float g_p [NREL * D];               // W2 W_r b2
__device__ float g_q [NREL * D];               // W2 W_r^T b2  (i.e. (b2 W_r W2^T)^T)
__device__ float g_c [NREL];                   // b2 W_r b2^T

// ---------------- f32x2 packed-FMA helpers ----------------
__device__ __forceinline__ unsigned long long dup2(float a) {
    unsigned long long r;
    asm("mov.b64 %0, {%1, %1};" : "=l"(r) : "f"(a));
    return r;
}
__device__ __forceinline__ void fma2(unsigned long long& c, unsigned long long a,
                                     unsigned long long b) {
    asm("fma.rn.f32x2 %0, %1, %2, %0;" : "+l"(c) : "l"(a), "l"(b));
}
__device__ __forceinline__ float2 unpack2(unsigned long long v) {
    float2 f;
    asm("mov.b64 {%0, %1}, %2;" : "=f"(f.x), "=f"(f.y) : "l"(v));
    return f;
}

// ---------------- prep: degrees, chained scan (CSR), edge permutation ----------------
__global__ void deg_kernel(const int* __restrict__ dst, int E) {
    int i = blockIdx.x * blockDim.x + threadIdx.x;
    if (i < E) atomicAdd(&g_rowcnt[dst[i]], 1);
}

// single-kernel chained-lookback exclusive scan; fuses dinv + cursor init.
// 8192 items/block; all blocks co-resident (<= 13 blocks), so the spin is safe.
__global__ __launch_bounds__(1024) void scan_kernel(int N, int E) {
    __shared__ int wsum[32];
    __shared__ int wpre[32];
    __shared__ int s_base;
    const int t = threadIdx.x, b = blockIdx.x;
    const int lane = t & 31, wid = t >> 5;
    const int idx0 = b * 8192 + t * 8;

    int v[8]; int tsum = 0;
#pragma unroll
    for (int i = 0; i < 8; i++) {
        int ii = idx0 + i;
        v[i] = (ii < N) ? g_rowcnt[ii] : 0;
        tsum += v[i];
    }
    int inc = tsum;
#pragma unroll
    for (int o = 1; o < 32; o <<= 1) {
        int x = __shfl_up_sync(~0u, inc, o);
        if (lane >= o) inc += x;
    }
    if (lane == 31) wsum[wid] = inc;
    __syncthreads();
    if (wid == 0) {
        int xi = wsum[lane];
#pragma unroll
        for (int o = 1; o < 32; o <<= 1) {
            int y = __shfl_up_sync(~0u, xi, o);
            if (lane >= o) xi += y;
        }
        wpre[lane] = xi;
    }
    __syncthreads();
    const int block_total = wpre[31];
    const int thread_excl = inc - tsum + (wid > 0 ? wpre[wid - 1] : 0);

    if (t == 0) {
        while (*(volatile int*)&g_chain[0] != b) { }
        int base = g_chain[1];
        s_base = base;
        g_chain[1] = base + block_total;
        __threadfence();
        *(volatile int*)&g_chain[0] = b + 1;
    }
    __syncthreads();

    int run = s_base + thread_excl;
#pragma unroll
    for (int i = 0; i < 8; i++) {
        int ii = idx0 + i;
        if (ii < N) {
            g_rowoff[ii] = run;
            g_ncur[ii]   = run;
            g_dinv[ii]   = (v[i] > 0) ? rsqrtf((float)v[i]) : 0.0f;
        }
        run += v[i];
    }
    if (b == 0 && t == 0) g_rowoff[N] = E;
}

// group edges by dst; pack (src, norm-weight) per edge
__global__ void eperm_kernel(const int* __restrict__ src, const int* __restrict__ dst, int E) {
    int e = blockIdx.x * blockDim.x + threadIdx.x;
    if (e < E) {
        int s = src[e], d = dst[e];
        int pos = atomicAdd(&g_ncur[d], 1);
        float w = g_dinv[s] * g_dinv[d];
        g_edata[pos] = make_int2(s, __float_as_int(w));
    }
}

// ---------------- fused relation counting sort (single block) ----------------
__global__ __launch_bounds__(1024) void relsort_kernel(const int* __restrict__ rel, int ES) {
    __shared__ int hist[NREL];
    const int t = threadIdx.x;
    if (t < NREL) hist[t] = 0;
    __syncthreads();
    for (int i = t; i < ES; i += 1024) atomicAdd(&hist[rel[i]], 1);
    __syncthreads();
    if (t == 0) {
        int s = 0;
        for (int r = 0; r < NREL; r++) { g_off[r] = s; int c = hist[r]; hist[r] = s; s += c; }
        g_off[NREL] = s;
    }
    __syncthreads();
    for (int i = t; i < ES; i += 1024) {
        int pos = atomicAdd(&hist[rel[i]], 1);
        g_perm[pos] = i;
    }
}

// ---------------- fp32x2 GEMM: C[M,128] = op(A)[M,128] @ W[128,128] ----------------
template <bool RELU>
__global__ __launch_bounds__(256, 2) void gemm_kernel(
    const float* __restrict__ A, const float* __restrict__ W,
    float* __restrict__ C, int M)
{
    __shared__ __align__(16) float As[32][D];   // transposed: As[k][m]
    __shared__ __align__(16) float Bs[32][D];   // Bs[k][n]
    const int tid = threadIdx.x;
    const int tx  = tid & 15;
    const int ty  = tid >> 4;
    const int base = blockIdx.x * 128;

    unsigned long long acc[8][4];
#pragma unroll
    for (int i = 0; i < 8; i++)
#pragma unroll
        for (int j = 0; j < 4; j++) acc[i][j] = 0ull;

#pragma unroll 1
    for (int kc = 0; kc < D; kc += 32) {
#pragma unroll
        for (int it = 0; it < 4; it++) {
            int idx = tid + it * 256;
            int r   = idx >> 3;
            int c4  = idx & 7;
            int gr  = base + r;
            float4 v = make_float4(0.f, 0.f, 0.f, 0.f);
            if (gr < M) v = *(const float4*)(A + (size_t)gr * D + kc + c4 * 4);
            if (RELU) {
                v.x = fmaxf(v.x, 0.f); v.y = fmaxf(v.y, 0.f);
                v.z = fmaxf(v.z, 0.f); v.w = fmaxf(v.w, 0.f);
            }
            int kk = c4 * 4;
            As[kk + 0][r] = v.x; As[kk + 1][r] = v.y;
            As[kk + 2][r] = v.z; As[kk + 3][r] = v.w;
        }
#pragma unroll
        for (int it = 0; it < 4; it++) {
            int idx = tid + it * 256;
            int k   = idx >> 5;
            int c4  = idx & 31;
            *(float4*)(&Bs[k][c4 * 4]) =
                *(const float4*)(W + (size_t)(kc + k) * D + c4 * 4);
        }
        __syncthreads();

#pragma unroll 8
        for (int k = 0; k < 32; k++) {
            float a[8];
            *(float4*)&a[0] = *(const float4*)&As[k][ty * 8];
            *(float4*)&a[4] = *(const float4*)&As[k][ty * 8 + 4];
            ulonglong2 b01 = *(const ulonglong2*)&Bs[k][tx * 8];
            ulonglong2 b23 = *(const ulonglong2*)&Bs[k][tx * 8 + 4];
#pragma unroll
            for (int i = 0; i < 8; i++) {
                unsigned long long ad = dup2(a[i]);
                fma2(acc[i][0], ad, b01.x);
                fma2(acc[i][1], ad, b01.y);
                fma2(acc[i][2], ad, b23.x);
                fma2(acc[i][3], ad, b23.y);
            }
        }
        __syncthreads();
    }

#pragma unroll
    for (int i = 0; i < 8; i++) {
        int gr = base + ty * 8 + i;
        if (gr < M) {
            float2 p0 = unpack2(acc[i][0]), p1 = unpack2(acc[i][1]);
            float2 p2 = unpack2(acc[i][2]), p3 = unpack2(acc[i][3]);
            *(float4*)(C + (size_t)gr * D + tx * 8)     = make_float4(p0.x, p0.y, p1.x, p1.y);
            *(float4*)(C + (size_t)gr * D + tx * 8 + 4) = make_float4(p2.x, p2.y, p3.x, p3.y);
        }
    }
}

// ---------------- small per-relation GEMM for score factorization ----------------
// C_r[128,128] = A_r @ op(B_r). blockIdx.x = relation. Fixed M=N=K=128.
template <bool BT>
__global__ __launch_bounds__(256) void prep_gemm_kernel(
    const float* __restrict__ Abase, long astride,
    const float* __restrict__ Bbase, long bstride,
    float* __restrict__ Cbase)
{
    __shared__ __align__(16) float As[32][D];
    __shared__ __align__(16) float Bs[32][D];
    const int rrel = blockIdx.x;
    const float* A = Abase + (size_t)rrel * astride;
    const float* B = Bbase + (size_t)rrel * bstride;
    float* C = Cbase + (size_t)rrel * D * D;

    const int tid = threadIdx.x;
    const int tx  = tid & 15;
    const int ty  = tid >> 4;

    unsigned long long acc[8][4];
#pragma unroll
    for (int i = 0; i < 8; i++)
#pragma unroll
        for (int j = 0; j < 4; j++) acc[i][j] = 0ull;

#pragma unroll 1
    for (int kc = 0; kc < D; kc += 32) {
#pragma unroll
        for (int it = 0; it < 4; it++) {
            int idx = tid + it * 256;
            int r   = idx >> 3;
            int c4  = idx & 7;
            float4 v = *(const float4*)(A + (size_t)r * D + kc + c4 * 4);
            int kk = c4 * 4;
            As[kk + 0][r] = v.x; As[kk + 1][r] = v.y;
            As[kk + 2][r] = v.z; As[kk + 3][r] = v.w;
        }
        if (BT) {
            // Bs[k][n] = B[n*D + k]  (transposed operand)
#pragma unroll
            for (int it = 0; it < 4; it++) {
                int idx = tid + it * 256;
                int n   = idx >> 3;
                int c4  = idx & 7;
                float4 v = *(const float4*)(B + (size_t)n * D + kc + c4 * 4);
                int kk = c4 * 4;
                Bs[kk + 0][n] = v.x; Bs[kk + 1][n] = v.y;
                Bs[kk + 2][n] = v.z; Bs[kk + 3][n] = v.w;
            }
        } else {
#pragma unroll
            for (int it = 0; it < 4; it++) {
                int idx = tid + it * 256;
                int k   = idx >> 5;
                int c4  = idx & 31;
                *(float4*)(&Bs[k][c4 * 4]) =
                    *(const float4*)(B + (size_t)(kc + k) * D + c4 * 4);
            }
        }
        __syncthreads();

#pragma unroll 8
        for (int k = 0; k < 32; k++) {
            float a[8];
            *(float4*)&a[0] = *(const float4*)&As[k][ty * 8];
            *(float4*)&a[4] = *(const float4*)&As[k][ty * 8 + 4];
            ulonglong2 b01 = *(const ulonglong2*)&Bs[k][tx * 8];
            ulonglong2 b23 = *(const ulonglong2*)&Bs[k][tx * 8 + 4];
#pragma unroll
            for (int i = 0; i < 8; i++) {
                unsigned long long ad = dup2(a[i]);
                fma2(acc[i][0], ad, b01.x);
                fma2(acc[i][1], ad, b01.y);
                fma2(acc[i][2], ad, b23.x);
                fma2(acc[i][3], ad, b23.y);
            }
        }
        __syncthreads();
    }

#pragma unroll
    for (int i = 0; i < 8; i++) {
        int gr = ty * 8 + i;
        float2 p0 = unpack2(acc[i][0]), p1 = unpack2(acc[i][1]);
        float2 p2 = unpack2(acc[i][2]), p3 = unpack2(acc[i][3]);
        *(float4*)(C + (size_t)gr * D + tx * 8)     = make_float4(p0.x, p0.y, p1.x, p1.y);
        *(float4*)(C + (size_t)gr * D + tx * 8 + 4) = make_float4(p2.x, p2.y, p3.x, p3.y);
    }
}

// ---------------- bias cross-terms: p_r, q_r, c_r ----------------
__global__ __launch_bounds__(128) void prep_vec_kernel(
    const float* __restrict__ W2, const float* __restrict__ relW,
    const float* __restrict__ b2)
{
    __shared__ float sb2[D], s1[D], s2[D];
    __shared__ float red[4];
    const int t = threadIdx.x;
    const int r = blockIdx.x;
    sb2[t] = b2[t];
    __syncthreads();
    const float* Wr = relW + (size_t)r * D * D;
    float a1 = 0.f, a2 = 0.f;
    for (int d = 0; d < D; d++) {
        a1 += Wr[t * D + d] * sb2[d];   // s1 = W_r b2
        a2 += sb2[d] * Wr[d * D + t];   // s2 = b2 W_r
    }
    s1[t] = a1; s2[t] = a2;
    __syncthreads();
    float p = 0.f, q = 0.f;
    for (int c = 0; c < D; c++) {
        p += W2[t * D + c] * s1[c];     // p[i] = sum_c W2[i,c] s1[c]
        q += W2[t * D + c] * s2[c];     // q[i] = sum_d W2[i,d] s2[d]
    }
    g_p[r * D + t] = p;
    g_q[r * D + t] = q;
    // c_r = s2 . b2
    float cc = a2 * sb2[t];
#pragma unroll
    for (int o = 16; o > 0; o >>= 1) cc += __shfl_down_sync(~0u, cc, o);
    if ((t & 31) == 0) red[t >> 5] = cc;
    __syncthreads();
    if (t == 0) g_c[r] = red[0] + red[1] + red[2] + red[3];
}

// ---------------- CSR aggregation: out[n] = (b?) + sum_e w_e * f(h[src_e]) ----------------
// one warp per node; lane handles 16B; atomic-free; 4-deep load pipeline.
template <bool RELU, bool BIAS>
__global__ __launch_bounds__(256) void agg_kernel(
    const float* __restrict__ h, const float* __restrict__ bias,
    float* __restrict__ outb, int N)
{
    int gt   = blockIdx.x * blockDim.x + threadIdx.x;
    int node = gt >> 5;
    int lane = gt & 31;
    if (node >= N) return;

    int e  = g_rowoff[node];
    int e1 = g_rowoff[node + 1];
    float4 acc = BIAS ? *(const float4*)(bias + lane * 4)
                      : make_float4(0.f, 0.f, 0.f, 0.f);

    for (; e + 4 <= e1; e += 4) {
        int2 d0 = g_edata[e];
        int2 d1 = g_edata[e + 1];
        int2 d2 = g_edata[e + 2];
        int2 d3 = g_edata[e + 3];
        float4 v0 = *(const float4*)(h + (size_t)d0.x * D + lane * 4);
        float4 v1 = *(const float4*)(h + (size_t)d1.x * D + lane * 4);
        float4 v2 = *(const float4*)(h + (size_t)d2.x * D + lane * 4);
        float4 v3 = *(const float4*)(h + (size_t)d3.x * D + lane * 4);
        if (RELU) {
            v0.x = fmaxf(v0.x, 0.f); v0.y = fmaxf(v0.y, 0.f); v0.z = fmaxf(v0.z, 0.f); v0.w = fmaxf(v0.w, 0.f);
            v1.x = fmaxf(v1.x, 0.f); v1.y = fmaxf(v1.y, 0.f); v1.z = fmaxf(v1.z, 0.f); v1.w = fmaxf(v1.w, 0.f);
            v2.x = fmaxf(v2.x, 0.f); v2.y = fmaxf(v2.y, 0.f); v2.z = fmaxf(v2.z, 0.f); v2.w = fmaxf(v2.w, 0.f);
            v3.x = fmaxf(v3.x, 0.f); v3.y = fmaxf(v3.y, 0.f); v3.z = fmaxf(v3.z, 0.f); v3.w = fmaxf(v3.w, 0.f);
        }
        float w0 = __int_as_float(d0.y), w1 = __int_as_float(d1.y);
        float w2 = __int_as_float(d2.y), w3 = __int_as_float(d3.y);
        acc.x = fmaf(w0, v0.x, acc.x); acc.y = fmaf(w0, v0.y, acc.y);
        acc.z = fmaf(w0, v0.z, acc.z); acc.w = fmaf(w0, v0.w, acc.w);
        acc.x = fmaf(w1, v1.x, acc.x); acc.y = fmaf(w1, v1.y, acc.y);
        acc.z = fmaf(w1, v1.z, acc.z); acc.w = fmaf(w1, v1.w, acc.w);
        acc.x = fmaf(w2, v2.x, acc.x); acc.y = fmaf(w2, v2.y, acc.y);
        acc.z = fmaf(w2, v2.z, acc.z); acc.w = fmaf(w2, v2.w, acc.w);
        acc.x = fmaf(w3, v3.x, acc.x); acc.y = fmaf(w3, v3.y, acc.y);
        acc.z = fmaf(w3, v3.z, acc.z); acc.w = fmaf(w3, v3.w, acc.w);
    }
    for (; e < e1; e++) {
        int2 d0 = g_edata[e];
        float4 v0 = *(const float4*)(h + (size_t)d0.x * D + lane * 4);
        if (RELU) {
            v0.x = fmaxf(v0.x, 0.f); v0.y = fmaxf(v0.y, 0.f);
            v0.z = fmaxf(v0.z, 0.f); v0.w = fmaxf(v0.w, 0.f);
        }
        float w0 = __int_as_float(d0.y);
        acc.x = fmaf(w0, v0.x, acc.x); acc.y = fmaf(w0, v0.y, acc.y);
        acc.z = fmaf(w0, v0.z, acc.z); acc.w = fmaf(w0, v0.w, acc.w);
    }
    *(float4*)(outb + (size_t)node * D + lane * 4) = acc;
}

// ---------------- scoring: s = th M_r tt^T + th.p_r + q_r.tt + c_r ----------------
__global__ __launch_bounds__(256, 2) void score_gemm_kernel(
    const float* __restrict__ t2,
    const int* __restrict__ head, const int* __restrict__ tail,
    float* __restrict__ out)
{
    __shared__ __align__(16) float As[32][D];
    __shared__ __align__(16) float Bs[32][D];
    __shared__ __align__(16) float sp[D];
    __shared__ __align__(16) float sq[D];
    __shared__ int sHead[128], sTail[128], sIdx[128];

    const int r     = blockIdx.y;
    const int start = g_off[r];
    const int end   = g_off[r + 1];
    const int t0    = start + blockIdx.x * 128;
    if (t0 >= end) return;

    const int tid = threadIdx.x;
    const int tx  = tid & 15;
    const int ty  = tid >> 4;

    if (tid < 128) {
        int t = t0 + tid;
        if (t < end) {
            int idx = g_perm[t];
            sIdx[tid]  = idx;
            sHead[tid] = head[idx];
            sTail[tid] = tail[idx];
        } else {
            sIdx[tid] = -1; sHead[tid] = 0; sTail[tid] = 0;
        }
        sp[tid] = g_p[r * D + tid];
        sq[tid] = g_q[r * D + tid];
    }
    __syncthreads();

    const float* Wr = g_M + (size_t)r * D * D;
    const float cr = g_c[r];

    unsigned long long acc[8][4];
#pragma unroll
    for (int i = 0; i < 8; i++)
#pragma unroll
        for (int j = 0; j < 4; j++) acc[i][j] = 0ull;

#pragma unroll 1
    for (int kc = 0; kc < D; kc += 32) {
#pragma unroll
        for (int it = 0; it < 4; it++) {
            int idx = tid + it * 256;
            int rr  = idx >> 3;
            int c4  = idx & 7;
            float4 v = *(const float4*)(t2 + (size_t)sHead[rr] * D + kc + c4 * 4);
            int kk = c4 * 4;
            As[kk + 0][rr] = v.x; As[kk + 1][rr] = v.y;
            As[kk + 2][rr] = v.z; As[kk + 3][rr] = v.w;
        }
#pragma unroll
        for (int it = 0; it < 4; it++) {
            int idx = tid + it * 256;
            int k   = idx >> 5;
            int c4  = idx & 31;
            *(float4*)(&Bs[k][c4 * 4]) =
                *(const float4*)(Wr + (size_t)(kc + k) * D + c4 * 4);
        }
        __syncthreads();

#pragma unroll 8
        for (int k = 0; k < 32; k++) {
            float a[8];
            *(float4*)&a[0] = *(const float4*)&As[k][ty * 8];
            *(float4*)&a[4] = *(const float4*)&As[k][ty * 8 + 4];
            ulonglong2 b01 = *(const ulonglong2*)&Bs[k][tx * 8];
            ulonglong2 b23 = *(const ulonglong2*)&Bs[k][tx * 8 + 4];
#pragma unroll
            for (int i = 0; i < 8; i++) {
                unsigned long long ad = dup2(a[i]);
                fma2(acc[i][0], ad, b01.x);
                fma2(acc[i][1], ad, b01.y);
                fma2(acc[i][2], ad, b23.x);
                fma2(acc[i][3], ad, b23.y);
            }
        }
        __syncthreads();
    }

    const float4 P0 = *(const float4*)&sp[tx * 8];
    const float4 P1 = *(const float4*)&sp[tx * 8 + 4];
    const float4 Q0 = *(const float4*)&sq[tx * 8];
    const float4 Q1 = *(const float4*)&sq[tx * 8 + 4];

#pragma unroll
    for (int i = 0; i < 8; i++) {
        int rr   = ty * 8 + i;
        int oidx = sIdx[rr];
        int hh   = sHead[rr];
        int tl   = sTail[rr];
        float4 z0 = *(const float4*)(t2 + (size_t)tl * D + tx * 8);
        float4 z1 = *(const float4*)(t2 + (size_t)tl * D + tx * 8 + 4);
        float4 h0 = *(const float4*)(t2 + (size_t)hh * D + tx * 8);
        float4 h1 = *(const float4*)(t2 + (size_t)hh * D + tx * 8 + 4);
        float2 p0 = unpack2(acc[i][0]), p1 = unpack2(acc[i][1]);
        float2 p2 = unpack2(acc[i][2]), p3 = unpack2(acc[i][3]);
        float p = p0.x * z0.x + p0.y * z0.y + p1.x * z0.z + p1.y * z0.w
                + p2.x * z1.x + p2.y * z1.y + p3.x * z1.z + p3.y * z1.w
                + h0.x * P0.x + h0.y * P0.y + h0.z * P0.z + h0.w * P0.w
                + h1.x * P1.x + h1.y * P1.y + h1.z * P1.z + h1.w * P1.w
                + z0.x * Q0.x + z0.y * Q0.y + z0.z * Q0.z + z0.w * Q0.w
                + z1.x * Q1.x + z1.y * Q1.y + z1.z * Q1.z + z1.w * Q1.w;
#pragma unroll
        for (int o = 8; o > 0; o >>= 1)
            p += __shfl_down_sync(0xffffffffu, p, o, 16);
        if (tx == 0 && oidx >= 0) out[oidx] = p + cr;
    }
}

// ---------------- launch ----------------
extern "C" void kernel_launch(void* const* d_in, const int* in_sizes, int n_in,
                              void* d_out, int out_size) {
    const float* x0   = (const float*)d_in[0];
    const float* W1   = (const float*)d_in[1];
    const float* b1   = (const float*)d_in[2];
    const float* W2   = (const float*)d_in[3];
    const float* b2   = (const float*)d_in[4];
    const float* relW = (const float*)d_in[5];
    const int*   edge = (const int*)  d_in[6];
    const int*   rel  = (const int*)  d_in[7];
    const int*   head = (const int*)  d_in[8];
    const int*   tail = (const int*)  d_in[9];
    float*       out  = (float*)d_out;

    const int N  = in_sizes[0] / D;
    const int E  = in_sizes[6] / 2;
    const int ES = in_sizes[7];
    const int R  = in_sizes[5] / (D * D);
    const int* src = edge;
    const int* dst = edge + E;

    float *ph = nullptr, *pa = nullptr, *pT1 = nullptr, *pM = nullptr;
    int *prowcnt = nullptr, *pchain = nullptr;
    cudaGetSymbolAddress((void**)&ph, g_h);
    cudaGetSymbolAddress((void**)&pa, g_a);
    cudaGetSymbolAddress((void**)&pT1, g_T1);
    cudaGetSymbolAddress((void**)&pM, g_M);
    cudaGetSymbolAddress((void**)&prowcnt, g_rowcnt);
    cudaGetSymbolAddress((void**)&pchain, g_chain);

    const int T = 256;
    const int scan_blocks = (N + 8191) / 8192;
    const int agg_blocks  = (int)(((long long)N * 32 + T - 1) / T);

    static cudaStream_t s_side = nullptr;
    static cudaEvent_t  ev_fork = nullptr, ev_csr = nullptr, ev_pre = nullptr;
    static bool tried = false;
    if (!tried) {
        tried = true;
        bool ok = (cudaStreamCreateWithFlags(&s_side, cudaStreamNonBlocking) == cudaSuccess)
               && (cudaEventCreateWithFlags(&ev_fork, cudaEventDisableTiming) == cudaSuccess)
               && (cudaEventCreateWithFlags(&ev_csr,  cudaEventDisableTiming) == cudaSuccess)
               && (cudaEventCreateWithFlags(&ev_pre,  cudaEventDisableTiming) == cudaSuccess);
        if (!ok) s_side = nullptr;
    }

    if (s_side) {
        cudaEventRecord(ev_fork, 0);
        cudaStreamWaitEvent(s_side, ev_fork, 0);

        // side stream: CSR build (critical) then relation sort + score factorization
        cudaMemsetAsync(prowcnt, 0, (size_t)N * sizeof(int), s_side);
        cudaMemsetAsync(pchain, 0, 2 * sizeof(int), s_side);
        deg_kernel<<<(E + T - 1) / T, T, 0, s_side>>>(dst, E);
        scan_kernel<<<scan_blocks, 1024, 0, s_side>>>(N, E);
        eperm_kernel<<<(E + T - 1) / T, T, 0, s_side>>>(src, dst, E);
        cudaEventRecord(ev_csr, s_side);

        relsort_kernel<<<1, 1024, 0, s_side>>>(rel, ES);
        prep_gemm_kernel<true ><<<R, 256, 0, s_side>>>(relW, (long)D * D, W2, 0L, pT1);
        prep_gemm_kernel<false><<<R, 256, 0, s_side>>>(W2, 0L, pT1, (long)D * D, pM);
        prep_vec_kernel<<<R, 128, 0, s_side>>>(W2, relW, b2);
        cudaEventRecord(ev_pre, s_side);

        // main stream: gemm1 overlaps CSR build
        gemm_kernel<false><<<(N + 127) / 128, 256>>>(x0, W1, ph, N);

        cudaStreamWaitEvent(0, ev_csr, 0);
        agg_kernel<false, true ><<<agg_blocks, T>>>(ph, b1, pa, N);   // a1 = b1 + Agg(h1)
        agg_kernel<true,  false><<<agg_blocks, T>>>(pa, b1, ph, N);   // t2 = Agg(relu(a1))

        cudaStreamWaitEvent(0, ev_pre, 0);
        dim3 sgrid((ES + 127) / 128, R);
        score_gemm_kernel<<<sgrid, 256>>>(ph, head, tail, out);
    } else {
        // serial fallback
        cudaMemsetAsync(prowcnt, 0, (size_t)N * sizeof(int), 0);
        cudaMemsetAsync(pchain, 0, 2 * sizeof(int), 0);
        deg_kernel<<<(E + T - 1) / T, T>>>(dst, E);
        scan_kernel<<<scan_blocks, 1024>>>(N, E);
        eperm_kernel<<<(E + T - 1) / T, T>>>(src, dst, E);
        relsort_kernel<<<1, 1024>>>(rel, ES);
        prep_gemm_kernel<true ><<<R, 256>>>(relW, (long)D * D, W2, 0L, pT1);
        prep_gemm_kernel<false><<<R, 256>>>(W2, 0L, pT1, (long)D * D, pM);
        prep_vec_kernel<<<R, 128>>>(W2, relW, b2);
        gemm_kernel<false><<<(N + 127) / 128, 256>>>(x0, W1, ph, N);
        agg_kernel<false, true ><<<agg_blocks, T>>>(ph, b1, pa, N);
        agg_kernel<true,  false><<<agg_blocks, T>>>(pa, b1, ph, N);
        dim3 sgrid((ES + 127) / 128, R);
        score_gemm_kernel<<<sgrid, 256>>>(ph, head, tail, out);
    }
}

// round 12
// speedup vs baseline: 2.4418x; 1.0265x over previous
#include <cuda_runtime.h>

#define D     128
#define NMAX  100000
#define EMAX  1600000
#define ESMAX 30000
#define NREL  16

// ---------------- device scratch (no allocations allowed) ----------------
__device__ float g_h[(size_t)NMAX * D];    // gemm1 out h1; later t2 = Agg(relu(a1))
__device__ float g_a[(size_t)NMAX * D];    // a1 = b1 + Agg(h1)
__device__ float g_dinv[NMAX];             // d^-1/2
__device__ int   g_rowcnt[NMAX];           // in-degree counts
__device__ int   g_rowoff[NMAX + 1];       // CSR row offsets (by dst)
__device__ int   g_ncur[NMAX];             // atomic cursors for edge permutation
__device__ int2  g_edata[EMAX];            // (src, w-bits), sorted by dst
__device__ int   g_off[NREL + 1];
__device__ int   g_perm[ESMAX];
__device__ int   g_chain[2];               // {flag, running sum} for chained scan
__device__ unsigned char g_used[NMAX];     // nodes referenced by head/tail
// score factorization scratch
__device__ float g_T1[(size_t)NREL * D * D];   // W_r @ W2^T
__device__ float g_M [(size_t)NREL * D * D];   // W2 @ W_r @ W2^T
__device__ float g_p [NREL * D];               // W2 W_r b2
__device__ float g_q [NREL * D];               // W2 W_r^T b2
__device__ float g_c [NREL];                   // b2 W_r b2^T

// ---------------- f32x2 packed-FMA helpers ----------------
__device__ __forceinline__ unsigned long long dup2(float a) {
    unsigned long long r;
    asm("mov.b64 %0, {%1, %1};" : "=l"(r) : "f"(a));
    return r;
}
__device__ __forceinline__ void fma2(unsigned long long& c, unsigned long long a,
                                     unsigned long long b) {
    asm("fma.rn.f32x2 %0, %1, %2, %0;" : "+l"(c) : "l"(a), "l"(b));
}
__device__ __forceinline__ float2 unpack2(unsigned long long v) {
    float2 f;
    asm("mov.b64 {%0, %1}, %2;" : "=f"(f.x), "=f"(f.y) : "l"(v));
    return f;
}

// ---------------- prep: degrees, chained scan (CSR), edge permutation ----------------
__global__ void deg_kernel(const int* __restrict__ dst, int E) {
    int i = blockIdx.x * blockDim.x + threadIdx.x;
    if (i < E) atomicAdd(&g_rowcnt[dst[i]], 1);
}

// mark nodes referenced by scored triples (idempotent plain stores)
__global__ void mark_kernel(const int* __restrict__ head, const int* __restrict__ tail, int ES) {
    int i = blockIdx.x * blockDim.x + threadIdx.x;
    if (i < ES) {
        g_used[head[i]] = 1;
        g_used[tail[i]] = 1;
    }
}

// single-kernel chained-lookback exclusive scan; fuses dinv + cursor init.
// 8192 items/block; all blocks co-resident (<= 13 blocks), so the spin is safe.
__global__ __launch_bounds__(1024) void scan_kernel(int N, int E) {
    __shared__ int wsum[32];
    __shared__ int wpre[32];
    __shared__ int s_base;
    const int t = threadIdx.x, b = blockIdx.x;
    const int lane = t & 31, wid = t >> 5;
    const int idx0 = b * 8192 + t * 8;

    int v[8]; int tsum = 0;
#pragma unroll
    for (int i = 0; i < 8; i++) {
        int ii = idx0 + i;
        v[i] = (ii < N) ? g_rowcnt[ii] : 0;
        tsum += v[i];
    }
    int inc = tsum;
#pragma unroll
    for (int o = 1; o < 32; o <<= 1) {
        int x = __shfl_up_sync(~0u, inc, o);
        if (lane >= o) inc += x;
    }
    if (lane == 31) wsum[wid] = inc;
    __syncthreads();
    if (wid == 0) {
        int xi = wsum[lane];
#pragma unroll
        for (int o = 1; o < 32; o <<= 1) {
            int y = __shfl_up_sync(~0u, xi, o);
            if (lane >= o) xi += y;
        }
        wpre[lane] = xi;
    }
    __syncthreads();
    const int block_total = wpre[31];
    const int thread_excl = inc - tsum + (wid > 0 ? wpre[wid - 1] : 0);

    if (t == 0) {
        while (*(volatile int*)&g_chain[0] != b) { }
        int base = g_chain[1];
        s_base = base;
        g_chain[1] = base + block_total;
        __threadfence();
        *(volatile int*)&g_chain[0] = b + 1;
    }
    __syncthreads();

    int run = s_base + thread_excl;
#pragma unroll
    for (int i = 0; i < 8; i++) {
        int ii = idx0 + i;
        if (ii < N) {
            g_rowoff[ii] = run;
            g_ncur[ii]   = run;
            g_dinv[ii]   = (v[i] > 0) ? rsqrtf((float)v[i]) : 0.0f;
        }
        run += v[i];
    }
    if (b == 0 && t == 0) g_rowoff[N] = E;
}

// group edges by dst; pack (src, norm-weight) per edge
__global__ void eperm_kernel(const int* __restrict__ src, const int* __restrict__ dst, int E) {
    int e = blockIdx.x * blockDim.x + threadIdx.x;
    if (e < E) {
        int s = src[e], d = dst[e];
        int pos = atomicAdd(&g_ncur[d], 1);
        float w = g_dinv[s] * g_dinv[d];
        g_edata[pos] = make_int2(s, __float_as_int(w));
    }
}

// ---------------- fused relation counting sort (single block) ----------------
__global__ __launch_bounds__(1024) void relsort_kernel(const int* __restrict__ rel, int ES) {
    __shared__ int hist[NREL];
    const int t = threadIdx.x;
    if (t < NREL) hist[t] = 0;
    __syncthreads();
    for (int i = t; i < ES; i += 1024) atomicAdd(&hist[rel[i]], 1);
    __syncthreads();
    if (t == 0) {
        int s = 0;
        for (int r = 0; r < NREL; r++) { g_off[r] = s; int c = hist[r]; hist[r] = s; s += c; }
        g_off[NREL] = s;
    }
    __syncthreads();
    for (int i = t; i < ES; i += 1024) {
        int pos = atomicAdd(&hist[rel[i]], 1);
        g_perm[pos] = i;
    }
}

// ---------------- fp32x2 GEMM: C[M,128] = op(A)[M,128] @ W[128,128] ----------------
template <bool RELU>
__global__ __launch_bounds__(256, 2) void gemm_kernel(
    const float* __restrict__ A, const float* __restrict__ W,
    float* __restrict__ C, int M)
{
    __shared__ __align__(16) float As[32][D];   // transposed: As[k][m]
    __shared__ __align__(16) float Bs[32][D];   // Bs[k][n]
    const int tid = threadIdx.x;
    const int tx  = tid & 15;
    const int ty  = tid >> 4;
    const int base = blockIdx.x * 128;

    unsigned long long acc[8][4];
#pragma unroll
    for (int i = 0; i < 8; i++)
#pragma unroll
        for (int j = 0; j < 4; j++) acc[i][j] = 0ull;

#pragma unroll 1
    for (int kc = 0; kc < D; kc += 32) {
#pragma unroll
        for (int it = 0; it < 4; it++) {
            int idx = tid + it * 256;
            int r   = idx >> 3;
            int c4  = idx & 7;
            int gr  = base + r;
            float4 v = make_float4(0.f, 0.f, 0.f, 0.f);
            if (gr < M) v = *(const float4*)(A + (size_t)gr * D + kc + c4 * 4);
            if (RELU) {
                v.x = fmaxf(v.x, 0.f); v.y = fmaxf(v.y, 0.f);
                v.z = fmaxf(v.z, 0.f); v.w = fmaxf(v.w, 0.f);
            }
            int kk = c4 * 4;
            As[kk + 0][r] = v.x; As[kk + 1][r] = v.y;
            As[kk + 2][r] = v.z; As[kk + 3][r] = v.w;
        }
#pragma unroll
        for (int it = 0; it < 4; it++) {
            int idx = tid + it * 256;
            int k   = idx >> 5;
            int c4  = idx & 31;
            *(float4*)(&Bs[k][c4 * 4]) =
                *(const float4*)(W + (size_t)(kc + k) * D + c4 * 4);
        }
        __syncthreads();

#pragma unroll 8
        for (int k = 0; k < 32; k++) {
            float a[8];
            *(float4*)&a[0] = *(const float4*)&As[k][ty * 8];
            *(float4*)&a[4] = *(const float4*)&As[k][ty * 8 + 4];
            ulonglong2 b01 = *(const ulonglong2*)&Bs[k][tx * 8];
            ulonglong2 b23 = *(const ulonglong2*)&Bs[k][tx * 8 + 4];
#pragma unroll
            for (int i = 0; i < 8; i++) {
                unsigned long long ad = dup2(a[i]);
                fma2(acc[i][0], ad, b01.x);
                fma2(acc[i][1], ad, b01.y);
                fma2(acc[i][2], ad, b23.x);
                fma2(acc[i][3], ad, b23.y);
            }
        }
        __syncthreads();
    }

#pragma unroll
    for (int i = 0; i < 8; i++) {
        int gr = base + ty * 8 + i;
        if (gr < M) {
            float2 p0 = unpack2(acc[i][0]), p1 = unpack2(acc[i][1]);
            float2 p2 = unpack2(acc[i][2]), p3 = unpack2(acc[i][3]);
            *(float4*)(C + (size_t)gr * D + tx * 8)     = make_float4(p0.x, p0.y, p1.x, p1.y);
            *(float4*)(C + (size_t)gr * D + tx * 8 + 4) = make_float4(p2.x, p2.y, p3.x, p3.y);
        }
    }
}

// ---------------- small per-relation GEMM for score factorization ----------------
template <bool BT>
__global__ __launch_bounds__(256) void prep_gemm_kernel(
    const float* __restrict__ Abase, long astride,
    const float* __restrict__ Bbase, long bstride,
    float* __restrict__ Cbase)
{
    __shared__ __align__(16) float As[32][D];
    __shared__ __align__(16) float Bs[32][D];
    const int rrel = blockIdx.x;
    const float* A = Abase + (size_t)rrel * astride;
    const float* B = Bbase + (size_t)rrel * bstride;
    float* C = Cbase + (size_t)rrel * D * D;

    const int tid = threadIdx.x;
    const int tx  = tid & 15;
    const int ty  = tid >> 4;

    unsigned long long acc[8][4];
#pragma unroll
    for (int i = 0; i < 8; i++)
#pragma unroll
        for (int j = 0; j < 4; j++) acc[i][j] = 0ull;

#pragma unroll 1
    for (int kc = 0; kc < D; kc += 32) {
#pragma unroll
        for (int it = 0; it < 4; it++) {
            int idx = tid + it * 256;
            int r   = idx >> 3;
            int c4  = idx & 7;
            float4 v = *(const float4*)(A + (size_t)r * D + kc + c4 * 4);
            int kk = c4 * 4;
            As[kk + 0][r] = v.x; As[kk + 1][r] = v.y;
            As[kk + 2][r] = v.z; As[kk + 3][r] = v.w;
        }
        if (BT) {
#pragma unroll
            for (int it = 0; it < 4; it++) {
                int idx = tid + it * 256;
                int n   = idx >> 3;
                int c4  = idx & 7;
                float4 v = *(const float4*)(B + (size_t)n * D + kc + c4 * 4);
                int kk = c4 * 4;
                Bs[kk + 0][n] = v.x; Bs[kk + 1][n] = v.y;
                Bs[kk + 2][n] = v.z; Bs[kk + 3][n] = v.w;
            }
        } else {
#pragma unroll
            for (int it = 0; it < 4; it++) {
                int idx = tid + it * 256;
                int k   = idx >> 5;
                int c4  = idx & 31;
                *(float4*)(&Bs[k][c4 * 4]) =
                    *(const float4*)(B + (size_t)(kc + k) * D + c4 * 4);
            }
        }
        __syncthreads();

#pragma unroll 8
        for (int k = 0; k < 32; k++) {
            float a[8];
            *(float4*)&a[0] = *(const float4*)&As[k][ty * 8];
            *(float4*)&a[4] = *(const float4*)&As[k][ty * 8 + 4];
            ulonglong2 b01 = *(const ulonglong2*)&Bs[k][tx * 8];
            ulonglong2 b23 = *(const ulonglong2*)&Bs[k][tx * 8 + 4];
#pragma unroll
            for (int i = 0; i < 8; i++) {
                unsigned long long ad = dup2(a[i]);
                fma2(acc[i][0], ad, b01.x);
                fma2(acc[i][1], ad, b01.y);
                fma2(acc[i][2], ad, b23.x);
                fma2(acc[i][3], ad, b23.y);
            }
        }
        __syncthreads();
    }

#pragma unroll
    for (int i = 0; i < 8; i++) {
        int gr = ty * 8 + i;
        float2 p0 = unpack2(acc[i][0]), p1 = unpack2(acc[i][1]);
        float2 p2 = unpack2(acc[i][2]), p3 = unpack2(acc[i][3]);
        *(float4*)(C + (size_t)gr * D + tx * 8)     = make_float4(p0.x, p0.y, p1.x, p1.y);
        *(float4*)(C + (size_t)gr * D + tx * 8 + 4) = make_float4(p2.x, p2.y, p3.x, p3.y);
    }
}

// ---------------- bias cross-terms: p_r, q_r, c_r ----------------
__global__ __launch_bounds__(128) void prep_vec_kernel(
    const float* __restrict__ W2, const float* __restrict__ relW,
    const float* __restrict__ b2)
{
    __shared__ float sb2[D], s1[D], s2[D];
    __shared__ float red[4];
    const int t = threadIdx.x;
    const int r = blockIdx.x;
    sb2[t] = b2[t];
    __syncthreads();
    const float* Wr = relW + (size_t)r * D * D;
    float a1 = 0.f, a2 = 0.f;
    for (int d = 0; d < D; d++) {
        a1 += Wr[t * D + d] * sb2[d];   // s1 = W_r b2
        a2 += sb2[d] * Wr[d * D + t];   // s2 = b2 W_r
    }
    s1[t] = a1; s2[t] = a2;
    __syncthreads();
    float p = 0.f, q = 0.f;
    for (int c = 0; c < D; c++) {
        p += W2[t * D + c] * s1[c];
        q += W2[t * D + c] * s2[c];
    }
    g_p[r * D + t] = p;
    g_q[r * D + t] = q;
    float cc = a2 * sb2[t];
#pragma unroll
    for (int o = 16; o > 0; o >>= 1) cc += __shfl_down_sync(~0u, cc, o);
    if ((t & 31) == 0) red[t >> 5] = cc;
    __syncthreads();
    if (t == 0) g_c[r] = red[0] + red[1] + red[2] + red[3];
}

// ---------------- CSR aggregation: out[n] = (b?) + sum_e w_e * f(h[src_e]) ----------------
// one warp per node; lane handles 16B; atomic-free; 4-deep load pipeline.
// SPARSE: skip nodes not referenced by any scored triple.
template <bool RELU, bool BIAS, bool SPARSE>
__global__ __launch_bounds__(256) void agg_kernel(
    const float* __restrict__ h, const float* __restrict__ bias,
    float* __restrict__ outb, int N)
{
    int gt   = blockIdx.x * blockDim.x + threadIdx.x;
    int node = gt >> 5;
    int lane = gt & 31;
    if (node >= N) return;
    if (SPARSE && !g_used[node]) return;

    int e  = g_rowoff[node];
    int e1 = g_rowoff[node + 1];
    float4 acc = BIAS ? *(const float4*)(bias + lane * 4)
                      : make_float4(0.f, 0.f, 0.f, 0.f);

    for (; e + 4 <= e1; e += 4) {
        int2 d0 = g_edata[e];
        int2 d1 = g_edata[e + 1];
        int2 d2 = g_edata[e + 2];
        int2 d3 = g_edata[e + 3];
        float4 v0 = *(const float4*)(h + (size_t)d0.x * D + lane * 4);
        float4 v1 = *(const float4*)(h + (size_t)d1.x * D + lane * 4);
        float4 v2 = *(const float4*)(h + (size_t)d2.x * D + lane * 4);
        float4 v3 = *(const float4*)(h + (size_t)d3.x * D + lane * 4);
        if (RELU) {
            v0.x = fmaxf(v0.x, 0.f); v0.y = fmaxf(v0.y, 0.f); v0.z = fmaxf(v0.z, 0.f); v0.w = fmaxf(v0.w, 0.f);
            v1.x = fmaxf(v1.x, 0.f); v1.y = fmaxf(v1.y, 0.f); v1.z = fmaxf(v1.z, 0.f); v1.w = fmaxf(v1.w, 0.f);
            v2.x = fmaxf(v2.x, 0.f); v2.y = fmaxf(v2.y, 0.f); v2.z = fmaxf(v2.z, 0.f); v2.w = fmaxf(v2.w, 0.f);
            v3.x = fmaxf(v3.x, 0.f); v3.y = fmaxf(v3.y, 0.f); v3.z = fmaxf(v3.z, 0.f); v3.w = fmaxf(v3.w, 0.f);
        }
        float w0 = __int_as_float(d0.y), w1 = __int_as_float(d1.y);
        float w2 = __int_as_float(d2.y), w3 = __int_as_float(d3.y);
        acc.x = fmaf(w0, v0.x, acc.x); acc.y = fmaf(w0, v0.y, acc.y);
        acc.z = fmaf(w0, v0.z, acc.z); acc.w = fmaf(w0, v0.w, acc.w);
        acc.x = fmaf(w1, v1.x, acc.x); acc.y = fmaf(w1, v1.y, acc.y);
        acc.z = fmaf(w1, v1.z, acc.z); acc.w = fmaf(w1, v1.w, acc.w);
        acc.x = fmaf(w2, v2.x, acc.x); acc.y = fmaf(w2, v2.y, acc.y);
        acc.z = fmaf(w2, v2.z, acc.z); acc.w = fmaf(w2, v2.w, acc.w);
        acc.x = fmaf(w3, v3.x, acc.x); acc.y = fmaf(w3, v3.y, acc.y);
        acc.z = fmaf(w3, v3.z, acc.z); acc.w = fmaf(w3, v3.w, acc.w);
    }
    for (; e < e1; e++) {
        int2 d0 = g_edata[e];
        float4 v0 = *(const float4*)(h + (size_t)d0.x * D + lane * 4);
        if (RELU) {
            v0.x = fmaxf(v0.x, 0.f); v0.y = fmaxf(v0.y, 0.f);
            v0.z = fmaxf(v0.z, 0.f); v0.w = fmaxf(v0.w, 0.f);
        }
        float w0 = __int_as_float(d0.y);
        acc.x = fmaf(w0, v0.x, acc.x); acc.y = fmaf(w0, v0.y, acc.y);
        acc.z = fmaf(w0, v0.z, acc.z); acc.w = fmaf(w0, v0.w, acc.w);
    }
    *(float4*)(outb + (size_t)node * D + lane * 4) = acc;
}

// ---------------- scoring: s = th M_r tt^T + th.p_r + q_r.tt + c_r ----------------
__global__ __launch_bounds__(256, 2) void score_gemm_kernel(
    const float* __restrict__ t2,
    const int* __restrict__ head, const int* __restrict__ tail,
    float* __restrict__ out)
{
    __shared__ __align__(16) float As[32][D];
    __shared__ __align__(16) float Bs[32][D];
    __shared__ __align__(16) float sp[D];
    __shared__ __align__(16) float sq[D];
    __shared__ int sHead[128], sTail[128], sIdx[128];

    const int r     = blockIdx.y;
    const int start = g_off[r];
    const int end   = g_off[r + 1];
    const int t0    = start + blockIdx.x * 128;
    if (t0 >= end) return;

    const int tid = threadIdx.x;
    const int tx  = tid & 15;
    const int ty  = tid >> 4;

    if (tid < 128) {
        int t = t0 + tid;
        if (t < end) {
            int idx = g_perm[t];
            sIdx[tid]  = idx;
            sHead[tid] = head[idx];
            sTail[tid] = tail[idx];
        } else {
            sIdx[tid] = -1; sHead[tid] = 0; sTail[tid] = 0;
        }
        sp[tid] = g_p[r * D + tid];
        sq[tid] = g_q[r * D + tid];
    }
    __syncthreads();

    const float* Wr = g_M + (size_t)r * D * D;
    const float cr = g_c[r];

    unsigned long long acc[8][4];
#pragma unroll
    for (int i = 0; i < 8; i++)
#pragma unroll
        for (int j = 0; j < 4; j++) acc[i][j] = 0ull;

#pragma unroll 1
    for (int kc = 0; kc < D; kc += 32) {
#pragma unroll
        for (int it = 0; it < 4; it++) {
            int idx = tid + it * 256;
            int rr  = idx >> 3;
            int c4  = idx & 7;
            float4 v = *(const float4*)(t2 + (size_t)sHead[rr] * D + kc + c4 * 4);
            int kk = c4 * 4;
            As[kk + 0][rr] = v.x; As[kk + 1][rr] = v.y;
            As[kk + 2][rr] = v.z; As[kk + 3][rr] = v.w;
        }
#pragma unroll
        for (int it = 0; it < 4; it++) {
            int idx = tid + it * 256;
            int k   = idx >> 5;
            int c4  = idx & 31;
            *(float4*)(&Bs[k][c4 * 4]) =
                *(const float4*)(Wr + (size_t)(kc + k) * D + c4 * 4);
        }
        __syncthreads();

#pragma unroll 8
        for (int k = 0; k < 32; k++) {
            float a[8];
            *(float4*)&a[0] = *(const float4*)&As[k][ty * 8];
            *(float4*)&a[4] = *(const float4*)&As[k][ty * 8 + 4];
            ulonglong2 b01 = *(const ulonglong2*)&Bs[k][tx * 8];
            ulonglong2 b23 = *(const ulonglong2*)&Bs[k][tx * 8 + 4];
#pragma unroll
            for (int i = 0; i < 8; i++) {
                unsigned long long ad = dup2(a[i]);
                fma2(acc[i][0], ad, b01.x);
                fma2(acc[i][1], ad, b01.y);
                fma2(acc[i][2], ad, b23.x);
                fma2(acc[i][3], ad, b23.y);
            }
        }
        __syncthreads();
    }

    const float4 P0 = *(const float4*)&sp[tx * 8];
    const float4 P1 = *(const float4*)&sp[tx * 8 + 4];
    const float4 Q0 = *(const float4*)&sq[tx * 8];
    const float4 Q1 = *(const float4*)&sq[tx * 8 + 4];

#pragma unroll
    for (int i = 0; i < 8; i++) {
        int rr   = ty * 8 + i;
        int oidx = sIdx[rr];
        int hh   = sHead[rr];
        int tl   = sTail[rr];
        float4 z0 = *(const float4*)(t2 + (size_t)tl * D + tx * 8);
        float4 z1 = *(const float4*)(t2 + (size_t)tl * D + tx * 8 + 4);
        float4 h0 = *(const float4*)(t2 + (size_t)hh * D + tx * 8);
        float4 h1 = *(const float4*)(t2 + (size_t)hh * D + tx * 8 + 4);
        float2 p0 = unpack2(acc[i][0]), p1 = unpack2(acc[i][1]);
        float2 p2 = unpack2(acc[i][2]), p3 = unpack2(acc[i][3]);
        float p = p0.x * z0.x + p0.y * z0.y + p1.x * z0.z + p1.y * z0.w
                + p2.x * z1.x + p2.y * z1.y + p3.x * z1.z + p3.y * z1.w
                + h0.x * P0.x + h0.y * P0.y + h0.z * P0.z + h0.w * P0.w
                + h1.x * P1.x + h1.y * P1.y + h1.z * P1.z + h1.w * P1.w
                + z0.x * Q0.x + z0.y * Q0.y + z0.z * Q0.z + z0.w * Q0.w
                + z1.x * Q1.x + z1.y * Q1.y + z1.z * Q1.z + z1.w * Q1.w;
#pragma unroll
        for (int o = 8; o > 0; o >>= 1)
            p += __shfl_down_sync(0xffffffffu, p, o, 16);
        if (tx == 0 && oidx >= 0) out[oidx] = p + cr;
    }
}

// ---------------- launch ----------------
extern "C" void kernel_launch(void* const* d_in, const int* in_sizes, int n_in,
                              void* d_out, int out_size) {
    const float* x0   = (const float*)d_in[0];
    const float* W1   = (const float*)d_in[1];
    const float* b1   = (const float*)d_in[2];
    const float* W2   = (const float*)d_in[3];
    const float* b2   = (const float*)d_in[4];
    const float* relW = (const float*)d_in[5];
    const int*   edge = (const int*)  d_in[6];
    const int*   rel  = (const int*)  d_in[7];
    const int*   head = (const int*)  d_in[8];
    const int*   tail = (const int*)  d_in[9];
    float*       out  = (float*)d_out;

    const int N  = in_sizes[0] / D;
    const int E  = in_sizes[6] / 2;
    const int ES = in_sizes[7];
    const int R  = in_sizes[5] / (D * D);
    const int* src = edge;
    const int* dst = edge + E;

    float *ph = nullptr, *pa = nullptr, *pT1 = nullptr, *pM = nullptr;
    int *prowcnt = nullptr, *pchain = nullptr;
    unsigned char* pused = nullptr;
    cudaGetSymbolAddress((void**)&ph, g_h);
    cudaGetSymbolAddress((void**)&pa, g_a);
    cudaGetSymbolAddress((void**)&pT1, g_T1);
    cudaGetSymbolAddress((void**)&pM, g_M);
    cudaGetSymbolAddress((void**)&prowcnt, g_rowcnt);
    cudaGetSymbolAddress((void**)&pchain, g_chain);
    cudaGetSymbolAddress((void**)&pused, g_used);

    const int T = 256;
    const int scan_blocks = (N + 8191) / 8192;
    const int agg_blocks  = (int)(((long long)N * 32 + T - 1) / T);

    static cudaStream_t s_side = nullptr;
    static cudaEvent_t  ev_fork = nullptr, ev_csr = nullptr, ev_pre = nullptr;
    static bool tried = false;
    if (!tried) {
        tried = true;
        bool ok = (cudaStreamCreateWithFlags(&s_side, cudaStreamNonBlocking) == cudaSuccess)
               && (cudaEventCreateWithFlags(&ev_fork, cudaEventDisableTiming) == cudaSuccess)
               && (cudaEventCreateWithFlags(&ev_csr,  cudaEventDisableTiming) == cudaSuccess)
               && (cudaEventCreateWithFlags(&ev_pre,  cudaEventDisableTiming) == cudaSuccess);
        if (!ok) s_side = nullptr;
    }

    if (s_side) {
        cudaEventRecord(ev_fork, 0);
        cudaStreamWaitEvent(s_side, ev_fork, 0);

        // side stream: CSR build + used-node marking (critical),
        // then relation sort + score factorization
        cudaMemsetAsync(prowcnt, 0, (size_t)N * sizeof(int), s_side);
        cudaMemsetAsync(pchain, 0, 2 * sizeof(int), s_side);
        cudaMemsetAsync(pused, 0, (size_t)N, s_side);
        mark_kernel<<<(ES + T - 1) / T, T, 0, s_side>>>(head, tail, ES);
        deg_kernel<<<(E + T - 1) / T, T, 0, s_side>>>(dst, E);
        scan_kernel<<<scan_blocks, 1024, 0, s_side>>>(N, E);
        eperm_kernel<<<(E + T - 1) / T, T, 0, s_side>>>(src, dst, E);
        cudaEventRecord(ev_csr, s_side);

        relsort_kernel<<<1, 1024, 0, s_side>>>(rel, ES);
        prep_gemm_kernel<true ><<<R, 256, 0, s_side>>>(relW, (long)D * D, W2, 0L, pT1);
        prep_gemm_kernel<false><<<R, 256, 0, s_side>>>(W2, 0L, pT1, (long)D * D, pM);
        prep_vec_kernel<<<R, 128, 0, s_side>>>(W2, relW, b2);
        cudaEventRecord(ev_pre, s_side);

        // main stream: gemm1 overlaps CSR build
        gemm_kernel<false><<<(N + 127) / 128, 256>>>(x0, W1, ph, N);

        cudaStreamWaitEvent(0, ev_csr, 0);
        agg_kernel<false, true , false><<<agg_blocks, T>>>(ph, b1, pa, N); // a1 = b1 + Agg(h1)
        agg_kernel<true,  false, true ><<<agg_blocks, T>>>(pa, b1, ph, N); // t2 = Agg(relu(a1)), used nodes only

        cudaStreamWaitEvent(0, ev_pre, 0);
        dim3 sgrid((ES + 127) / 128, R);
        score_gemm_kernel<<<sgrid, 256>>>(ph, head, tail, out);
    } else {
        // serial fallback
        cudaMemsetAsync(prowcnt, 0, (size_t)N * sizeof(int), 0);
        cudaMemsetAsync(pchain, 0, 2 * sizeof(int), 0);
        cudaMemsetAsync(pused, 0, (size_t)N, 0);
        mark_kernel<<<(ES + T - 1) / T, T>>>(head, tail, ES);
        deg_kernel<<<(E + T - 1) / T, T>>>(dst, E);
        scan_kernel<<<scan_blocks, 1024>>>(N, E);
        eperm_kernel<<<(E + T - 1) / T, T>>>(src, dst, E);
        relsort_kernel<<<1, 1024>>>(rel, ES);
        prep_gemm_kernel<true ><<<R, 256>>>(relW, (long)D * D, W2, 0L, pT1);
        prep_gemm_kernel<false><<<R, 256>>>(W2, 0L, pT1, (long)D * D, pM);
        prep_vec_kernel<<<R, 128>>>(W2, relW, b2);
        gemm_kernel<false><<<(N + 127) / 128, 256>>>(x0, W1, ph, N);
        agg_kernel<false, true , false><<<agg_blocks, T>>>(ph, b1, pa, N);
        agg_kernel<true,  false, true ><<<agg_blocks, T>>>(pa, b1, ph, N);
        dim3 sgrid((ES + 127) / 128, R);
        score_gemm_kernel<<<sgrid, 256>>>(ph, head, tail, out);
    }
}

// round 13
// speedup vs baseline: 2.4854x; 1.0179x over previous
#include <cuda_runtime.h>

#define D     128
#define NMAX  100000
#define EMAX  1600000
#define ESMAX 30000
#define NREL  16

// ---------------- device scratch (no allocations allowed) ----------------
__device__ float g_h[(size_t)NMAX * D];    // gemm1 out h1; later t2 = Agg(relu(a1))
__device__ float g_a[(size_t)NMAX * D];    // relu_a1 = relu(b1 + Agg(h1))
__device__ float g_dinv[NMAX];             // d^-1/2
__device__ int   g_rowcnt[NMAX];           // in-degree counts
__device__ int   g_rowoff[NMAX + 1];       // CSR row offsets (by dst)
__device__ int   g_ncur[NMAX];             // atomic cursors for edge permutation
__device__ int2  g_edata[EMAX];            // (src, w-bits), sorted by dst
__device__ int   g_off[NREL + 1];
__device__ int   g_perm[ESMAX];
__device__ int   g_chain[2];               // {flag, running sum} for chained scan
__device__ unsigned char g_used[NMAX];     // nodes referenced by head/tail
// score factorization scratch
__device__ float g_T1[(size_t)NREL * D * D];   // W_r @ W2^T
__device__ float g_M [(size_t)NREL * D * D];   // W2 @ W_r @ W2^T
__device__ float g_p [NREL * D];               // W2 W_r b2
__device__ float g_q [NREL * D];               // W2 W_r^T b2
__device__ float g_c [NREL];                   // b2 W_r b2^T

// ---------------- f32x2 packed-FMA helpers ----------------
__device__ __forceinline__ unsigned long long dup2(float a) {
    unsigned long long r;
    asm("mov.b64 %0, {%1, %1};" : "=l"(r) : "f"(a));
    return r;
}
__device__ __forceinline__ void fma2(unsigned long long& c, unsigned long long a,
                                     unsigned long long b) {
    asm("fma.rn.f32x2 %0, %1, %2, %0;" : "+l"(c) : "l"(a), "l"(b));
}
__device__ __forceinline__ float2 unpack2(unsigned long long v) {
    float2 f;
    asm("mov.b64 {%0, %1}, %2;" : "=f"(f.x), "=f"(f.y) : "l"(v));
    return f;
}

// ---------------- fused zero: rowcnt + used + chain in one launch ----------------
__global__ void zero_kernel(int N) {
    int i = blockIdx.x * blockDim.x + threadIdx.x;
    if (i < N) g_rowcnt[i] = 0;
    int words = N >> 2;
    if (i < words) ((int*)g_used)[i] = 0;
    if (i == 0) {
        g_chain[0] = 0; g_chain[1] = 0;
        for (int b = words << 2; b < N; b++) g_used[b] = 0;
    }
}

// ---------------- fused degrees + used-node marking ----------------
__global__ void degmark_kernel(const int* __restrict__ dst,
                               const int* __restrict__ head,
                               const int* __restrict__ tail, int E, int ES) {
    int i = blockIdx.x * blockDim.x + threadIdx.x;
    if (i < E) atomicAdd(&g_rowcnt[dst[i]], 1);
    if (i < ES) {
        g_used[head[i]] = 1;
        g_used[tail[i]] = 1;
    }
}

// single-kernel chained-lookback exclusive scan; fuses dinv + cursor init.
// 8192 items/block; all blocks co-resident (<= 13 blocks), so the spin is safe.
__global__ __launch_bounds__(1024) void scan_kernel(int N, int E) {
    __shared__ int wsum[32];
    __shared__ int wpre[32];
    __shared__ int s_base;
    const int t = threadIdx.x, b = blockIdx.x;
    const int lane = t & 31, wid = t >> 5;
    const int idx0 = b * 8192 + t * 8;

    int v[8]; int tsum = 0;
#pragma unroll
    for (int i = 0; i < 8; i++) {
        int ii = idx0 + i;
        v[i] = (ii < N) ? g_rowcnt[ii] : 0;
        tsum += v[i];
    }
    int inc = tsum;
#pragma unroll
    for (int o = 1; o < 32; o <<= 1) {
        int x = __shfl_up_sync(~0u, inc, o);
        if (lane >= o) inc += x;
    }
    if (lane == 31) wsum[wid] = inc;
    __syncthreads();
    if (wid == 0) {
        int xi = wsum[lane];
#pragma unroll
        for (int o = 1; o < 32; o <<= 1) {
            int y = __shfl_up_sync(~0u, xi, o);
            if (lane >= o) xi += y;
        }
        wpre[lane] = xi;
    }
    __syncthreads();
    const int block_total = wpre[31];
    const int thread_excl = inc - tsum + (wid > 0 ? wpre[wid - 1] : 0);

    if (t == 0) {
        while (*(volatile int*)&g_chain[0] != b) { }
        int base = g_chain[1];
        s_base = base;
        g_chain[1] = base + block_total;
        __threadfence();
        *(volatile int*)&g_chain[0] = b + 1;
    }
    __syncthreads();

    int run = s_base + thread_excl;
#pragma unroll
    for (int i = 0; i < 8; i++) {
        int ii = idx0 + i;
        if (ii < N) {
            g_rowoff[ii] = run;
            g_ncur[ii]   = run;
            g_dinv[ii]   = (v[i] > 0) ? rsqrtf((float)v[i]) : 0.0f;
        }
        run += v[i];
    }
    if (b == 0 && t == 0) g_rowoff[N] = E;
}

// group edges by dst; pack (src, norm-weight); 2 edges/thread, int2 loads
__global__ void eperm_kernel(const int* __restrict__ src, const int* __restrict__ dst, int E) {
    int e = (blockIdx.x * blockDim.x + threadIdx.x) * 2;
    if (e + 1 < E) {
        int2 s2 = *(const int2*)(src + e);
        int2 d2 = *(const int2*)(dst + e);
        int p0 = atomicAdd(&g_ncur[d2.x], 1);
        int p1 = atomicAdd(&g_ncur[d2.y], 1);
        float w0 = g_dinv[s2.x] * g_dinv[d2.x];
        float w1 = g_dinv[s2.y] * g_dinv[d2.y];
        g_edata[p0] = make_int2(s2.x, __float_as_int(w0));
        g_edata[p1] = make_int2(s2.y, __float_as_int(w1));
    } else if (e < E) {
        int s = src[e], d = dst[e];
        int pos = atomicAdd(&g_ncur[d], 1);
        float w = g_dinv[s] * g_dinv[d];
        g_edata[pos] = make_int2(s, __float_as_int(w));
    }
}

// ---------------- fused relation counting sort (single block) ----------------
__global__ __launch_bounds__(1024) void relsort_kernel(const int* __restrict__ rel, int ES) {
    __shared__ int hist[NREL];
    const int t = threadIdx.x;
    if (t < NREL) hist[t] = 0;
    __syncthreads();
    for (int i = t; i < ES; i += 1024) atomicAdd(&hist[rel[i]], 1);
    __syncthreads();
    if (t == 0) {
        int s = 0;
        for (int r = 0; r < NREL; r++) { g_off[r] = s; int c = hist[r]; hist[r] = s; s += c; }
        g_off[NREL] = s;
    }
    __syncthreads();
    for (int i = t; i < ES; i += 1024) {
        int pos = atomicAdd(&hist[rel[i]], 1);
        g_perm[pos] = i;
    }
}

// ---------------- fp32x2 GEMM: C[M,128] = A[M,128] @ W[128,128] ----------------
__global__ __launch_bounds__(256, 2) void gemm_kernel(
    const float* __restrict__ A, const float* __restrict__ W,
    float* __restrict__ C, int M)
{
    __shared__ __align__(16) float As[32][D];   // transposed: As[k][m]
    __shared__ __align__(16) float Bs[32][D];   // Bs[k][n]
    const int tid = threadIdx.x;
    const int tx  = tid & 15;
    const int ty  = tid >> 4;
    const int base = blockIdx.x * 128;

    unsigned long long acc[8][4];
#pragma unroll
    for (int i = 0; i < 8; i++)
#pragma unroll
        for (int j = 0; j < 4; j++) acc[i][j] = 0ull;

#pragma unroll 1
    for (int kc = 0; kc < D; kc += 32) {
#pragma unroll
        for (int it = 0; it < 4; it++) {
            int idx = tid + it * 256;
            int r   = idx >> 3;
            int c4  = idx & 7;
            int gr  = base + r;
            float4 v = make_float4(0.f, 0.f, 0.f, 0.f);
            if (gr < M) v = *(const float4*)(A + (size_t)gr * D + kc + c4 * 4);
            int kk = c4 * 4;
            As[kk + 0][r] = v.x; As[kk + 1][r] = v.y;
            As[kk + 2][r] = v.z; As[kk + 3][r] = v.w;
        }
#pragma unroll
        for (int it = 0; it < 4; it++) {
            int idx = tid + it * 256;
            int k   = idx >> 5;
            int c4  = idx & 31;
            *(float4*)(&Bs[k][c4 * 4]) =
                *(const float4*)(W + (size_t)(kc + k) * D + c4 * 4);
        }
        __syncthreads();

#pragma unroll 8
        for (int k = 0; k < 32; k++) {
            float a[8];
            *(float4*)&a[0] = *(const float4*)&As[k][ty * 8];
            *(float4*)&a[4] = *(const float4*)&As[k][ty * 8 + 4];
            ulonglong2 b01 = *(const ulonglong2*)&Bs[k][tx * 8];
            ulonglong2 b23 = *(const ulonglong2*)&Bs[k][tx * 8 + 4];
#pragma unroll
            for (int i = 0; i < 8; i++) {
                unsigned long long ad = dup2(a[i]);
                fma2(acc[i][0], ad, b01.x);
                fma2(acc[i][1], ad, b01.y);
                fma2(acc[i][2], ad, b23.x);
                fma2(acc[i][3], ad, b23.y);
            }
        }
        __syncthreads();
    }

#pragma unroll
    for (int i = 0; i < 8; i++) {
        int gr = base + ty * 8 + i;
        if (gr < M) {
            float2 p0 = unpack2(acc[i][0]), p1 = unpack2(acc[i][1]);
            float2 p2 = unpack2(acc[i][2]), p3 = unpack2(acc[i][3]);
            *(float4*)(C + (size_t)gr * D + tx * 8)     = make_float4(p0.x, p0.y, p1.x, p1.y);
            *(float4*)(C + (size_t)gr * D + tx * 8 + 4) = make_float4(p2.x, p2.y, p3.x, p3.y);
        }
    }
}

// ---------------- small per-relation GEMM for score factorization ----------------
template <bool BT>
__global__ __launch_bounds__(256) void prep_gemm_kernel(
    const float* __restrict__ Abase, long astride,
    const float* __restrict__ Bbase, long bstride,
    float* __restrict__ Cbase)
{
    __shared__ __align__(16) float As[32][D];
    __shared__ __align__(16) float Bs[32][D];
    const int rrel = blockIdx.x;
    const float* A = Abase + (size_t)rrel * astride;
    const float* B = Bbase + (size_t)rrel * bstride;
    float* C = Cbase + (size_t)rrel * D * D;

    const int tid = threadIdx.x;
    const int tx  = tid & 15;
    const int ty  = tid >> 4;

    unsigned long long acc[8][4];
#pragma unroll
    for (int i = 0; i < 8; i++)
#pragma unroll
        for (int j = 0; j < 4; j++) acc[i][j] = 0ull;

#pragma unroll 1
    for (int kc = 0; kc < D; kc += 32) {
#pragma unroll
        for (int it = 0; it < 4; it++) {
            int idx = tid + it * 256;
            int r   = idx >> 3;
            int c4  = idx & 7;
            float4 v = *(const float4*)(A + (size_t)r * D + kc + c4 * 4);
            int kk = c4 * 4;
            As[kk + 0][r] = v.x; As[kk + 1][r] = v.y;
            As[kk + 2][r] = v.z; As[kk + 3][r] = v.w;
        }
        if (BT) {
#pragma unroll
            for (int it = 0; it < 4; it++) {
                int idx = tid + it * 256;
                int n   = idx >> 3;
                int c4  = idx & 7;
                float4 v = *(const float4*)(B + (size_t)n * D + kc + c4 * 4);
                int kk = c4 * 4;
                Bs[kk + 0][n] = v.x; Bs[kk + 1][n] = v.y;
                Bs[kk + 2][n] = v.z; Bs[kk + 3][n] = v.w;
            }
        } else {
#pragma unroll
            for (int it = 0; it < 4; it++) {
                int idx = tid + it * 256;
                int k   = idx >> 5;
                int c4  = idx & 31;
                *(float4*)(&Bs[k][c4 * 4]) =
                    *(const float4*)(B + (size_t)(kc + k) * D + c4 * 4);
            }
        }
        __syncthreads();

#pragma unroll 8
        for (int k = 0; k < 32; k++) {
            float a[8];
            *(float4*)&a[0] = *(const float4*)&As[k][ty * 8];
            *(float4*)&a[4] = *(const float4*)&As[k][ty * 8 + 4];
            ulonglong2 b01 = *(const ulonglong2*)&Bs[k][tx * 8];
            ulonglong2 b23 = *(const ulonglong2*)&Bs[k][tx * 8 + 4];
#pragma unroll
            for (int i = 0; i < 8; i++) {
                unsigned long long ad = dup2(a[i]);
                fma2(acc[i][0], ad, b01.x);
                fma2(acc[i][1], ad, b01.y);
                fma2(acc[i][2], ad, b23.x);
                fma2(acc[i][3], ad, b23.y);
            }
        }
        __syncthreads();
    }

#pragma unroll
    for (int i = 0; i < 8; i++) {
        int gr = ty * 8 + i;
        float2 p0 = unpack2(acc[i][0]), p1 = unpack2(acc[i][1]);
        float2 p2 = unpack2(acc[i][2]), p3 = unpack2(acc[i][3]);
        *(float4*)(C + (size_t)gr * D + tx * 8)     = make_float4(p0.x, p0.y, p1.x, p1.y);
        *(float4*)(C + (size_t)gr * D + tx * 8 + 4) = make_float4(p2.x, p2.y, p3.x, p3.y);
    }
}

// ---------------- bias cross-terms: p_r, q_r, c_r ----------------
__global__ __launch_bounds__(128) void prep_vec_kernel(
    const float* __restrict__ W2, const float* __restrict__ relW,
    const float* __restrict__ b2)
{
    __shared__ float sb2[D], s1[D], s2[D];
    __shared__ float red[4];
    const int t = threadIdx.x;
    const int r = blockIdx.x;
    sb2[t] = b2[t];
    __syncthreads();
    const float* Wr = relW + (size_t)r * D * D;
    float a1 = 0.f, a2 = 0.f;
    for (int d = 0; d < D; d++) {
        a1 += Wr[t * D + d] * sb2[d];   // s1 = W_r b2
        a2 += sb2[d] * Wr[d * D + t];   // s2 = b2 W_r
    }
    s1[t] = a1; s2[t] = a2;
    __syncthreads();
    float p = 0.f, q = 0.f;
    for (int c = 0; c < D; c++) {
        p += W2[t * D + c] * s1[c];
        q += W2[t * D + c] * s2[c];
    }
    g_p[r * D + t] = p;
    g_q[r * D + t] = q;
    float cc = a2 * sb2[t];
#pragma unroll
    for (int o = 16; o > 0; o >>= 1) cc += __shfl_down_sync(~0u, cc, o);
    if ((t & 31) == 0) red[t >> 5] = cc;
    __syncthreads();
    if (t == 0) g_c[r] = red[0] + red[1] + red[2] + red[3];
}

// ---------------- CSR aggregation ----------------
// out[n] = relu?( bias? + sum_e w_e * h[src_e] ); one warp per node; atomic-free.
// SPARSE: skip nodes not referenced by any scored triple.
template <bool BIAS, bool SPARSE, bool RELU_OUT>
__global__ __launch_bounds__(256) void agg_kernel(
    const float* __restrict__ h, const float* __restrict__ bias,
    float* __restrict__ outb, int N)
{
    int gt   = blockIdx.x * blockDim.x + threadIdx.x;
    int node = gt >> 5;
    int lane = gt & 31;
    if (node >= N) return;
    if (SPARSE && !g_used[node]) return;

    int e  = __ldg(&g_rowoff[node]);
    int e1 = __ldg(&g_rowoff[node + 1]);
    float4 acc = BIAS ? *(const float4*)(bias + lane * 4)
                      : make_float4(0.f, 0.f, 0.f, 0.f);

    for (; e + 4 <= e1; e += 4) {
        int2 d0 = g_edata[e];
        int2 d1 = g_edata[e + 1];
        int2 d2 = g_edata[e + 2];
        int2 d3 = g_edata[e + 3];
        float4 v0 = *(const float4*)(h + (size_t)d0.x * D + lane * 4);
        float4 v1 = *(const float4*)(h + (size_t)d1.x * D + lane * 4);
        float4 v2 = *(const float4*)(h + (size_t)d2.x * D + lane * 4);
        float4 v3 = *(const float4*)(h + (size_t)d3.x * D + lane * 4);
        float w0 = __int_as_float(d0.y), w1 = __int_as_float(d1.y);
        float w2 = __int_as_float(d2.y), w3 = __int_as_float(d3.y);
        acc.x = fmaf(w0, v0.x, acc.x); acc.y = fmaf(w0, v0.y, acc.y);
        acc.z = fmaf(w0, v0.z, acc.z); acc.w = fmaf(w0, v0.w, acc.w);
        acc.x = fmaf(w1, v1.x, acc.x); acc.y = fmaf(w1, v1.y, acc.y);
        acc.z = fmaf(w1, v1.z, acc.z); acc.w = fmaf(w1, v1.w, acc.w);
        acc.x = fmaf(w2, v2.x, acc.x); acc.y = fmaf(w2, v2.y, acc.y);
        acc.z = fmaf(w2, v2.z, acc.z); acc.w = fmaf(w2, v2.w, acc.w);
        acc.x = fmaf(w3, v3.x, acc.x); acc.y = fmaf(w3, v3.y, acc.y);
        acc.z = fmaf(w3, v3.z, acc.z); acc.w = fmaf(w3, v3.w, acc.w);
    }
    for (; e < e1; e++) {
        int2 d0 = g_edata[e];
        float4 v0 = *(const float4*)(h + (size_t)d0.x * D + lane * 4);
        float w0 = __int_as_float(d0.y);
        acc.x = fmaf(w0, v0.x, acc.x); acc.y = fmaf(w0, v0.y, acc.y);
        acc.z = fmaf(w0, v0.z, acc.z); acc.w = fmaf(w0, v0.w, acc.w);
    }
    if (RELU_OUT) {
        acc.x = fmaxf(acc.x, 0.f); acc.y = fmaxf(acc.y, 0.f);
        acc.z = fmaxf(acc.z, 0.f); acc.w = fmaxf(acc.w, 0.f);
    }
    *(float4*)(outb + (size_t)node * D + lane * 4) = acc;
}

// ---------------- scoring: s = th M_r tt^T + th.p_r + q_r.tt + c_r ----------------
__global__ __launch_bounds__(256, 2) void score_gemm_kernel(
    const float* __restrict__ t2,
    const int* __restrict__ head, const int* __restrict__ tail,
    float* __restrict__ out)
{
    __shared__ __align__(16) float As[32][D];
    __shared__ __align__(16) float Bs[32][D];
    __shared__ __align__(16) float sp[D];
    __shared__ __align__(16) float sq[D];
    __shared__ int sHead[128], sTail[128], sIdx[128];

    const int r     = blockIdx.y;
    const int start = g_off[r];
    const int end   = g_off[r + 1];
    const int t0    = start + blockIdx.x * 128;
    if (t0 >= end) return;

    const int tid = threadIdx.x;
    const int tx  = tid & 15;
    const int ty  = tid >> 4;

    if (tid < 128) {
        int t = t0 + tid;
        if (t < end) {
            int idx = g_perm[t];
            sIdx[tid]  = idx;
            sHead[tid] = head[idx];
            sTail[tid] = tail[idx];
        } else {
            sIdx[tid] = -1; sHead[tid] = 0; sTail[tid] = 0;
        }
        sp[tid] = g_p[r * D + tid];
        sq[tid] = g_q[r * D + tid];
    }
    __syncthreads();

    const float* Wr = g_M + (size_t)r * D * D;
    const float cr = g_c[r];

    unsigned long long acc[8][4];
#pragma unroll
    for (int i = 0; i < 8; i++)
#pragma unroll
        for (int j = 0; j < 4; j++) acc[i][j] = 0ull;

#pragma unroll 1
    for (int kc = 0; kc < D; kc += 32) {
#pragma unroll
        for (int it = 0; it < 4; it++) {
            int idx = tid + it * 256;
            int rr  = idx >> 3;
            int c4  = idx & 7;
            float4 v = *(const float4*)(t2 + (size_t)sHead[rr] * D + kc + c4 * 4);
            int kk = c4 * 4;
            As[kk + 0][rr] = v.x; As[kk + 1][rr] = v.y;
            As[kk + 2][rr] = v.z; As[kk + 3][rr] = v.w;
        }
#pragma unroll
        for (int it = 0; it < 4; it++) {
            int idx = tid + it * 256;
            int k   = idx >> 5;
            int c4  = idx & 31;
            *(float4*)(&Bs[k][c4 * 4]) =
                *(const float4*)(Wr + (size_t)(kc + k) * D + c4 * 4);
        }
        __syncthreads();

#pragma unroll 8
        for (int k = 0; k < 32; k++) {
            float a[8];
            *(float4*)&a[0] = *(const float4*)&As[k][ty * 8];
            *(float4*)&a[4] = *(const float4*)&As[k][ty * 8 + 4];
            ulonglong2 b01 = *(const ulonglong2*)&Bs[k][tx * 8];
            ulonglong2 b23 = *(const ulonglong2*)&Bs[k][tx * 8 + 4];
#pragma unroll
            for (int i = 0; i < 8; i++) {
                unsigned long long ad = dup2(a[i]);
                fma2(acc[i][0], ad, b01.x);
                fma2(acc[i][1], ad, b01.y);
                fma2(acc[i][2], ad, b23.x);
                fma2(acc[i][3], ad, b23.y);
            }
        }
        __syncthreads();
    }

    const float4 P0 = *(const float4*)&sp[tx * 8];
    const float4 P1 = *(const float4*)&sp[tx * 8 + 4];
    const float4 Q0 = *(const float4*)&sq[tx * 8];
    const float4 Q1 = *(const float4*)&sq[tx * 8 + 4];

#pragma unroll
    for (int i = 0; i < 8; i++) {
        int rr   = ty * 8 + i;
        int oidx = sIdx[rr];
        int hh   = sHead[rr];
        int tl   = sTail[rr];
        float4 z0 = *(const float4*)(t2 + (size_t)tl * D + tx * 8);
        float4 z1 = *(const float4*)(t2 + (size_t)tl * D + tx * 8 + 4);
        float4 h0 = *(const float4*)(t2 + (size_t)hh * D + tx * 8);
        float4 h1 = *(const float4*)(t2 + (size_t)hh * D + tx * 8 + 4);
        float2 p0 = unpack2(acc[i][0]), p1 = unpack2(acc[i][1]);
        float2 p2 = unpack2(acc[i][2]), p3 = unpack2(acc[i][3]);
        float p = p0.x * z0.x + p0.y * z0.y + p1.x * z0.z + p1.y * z0.w
                + p2.x * z1.x + p2.y * z1.y + p3.x * z1.z + p3.y * z1.w
                + h0.x * P0.x + h0.y * P0.y + h0.z * P0.z + h0.w * P0.w
                + h1.x * P1.x + h1.y * P1.y + h1.z * P1.z + h1.w * P1.w
                + z0.x * Q0.x + z0.y * Q0.y + z0.z * Q0.z + z0.w * Q0.w
                + z1.x * Q1.x + z1.y * Q1.y + z1.z * Q1.z + z1.w * Q1.w;
#pragma unroll
        for (int o = 8; o > 0; o >>= 1)
            p += __shfl_down_sync(0xffffffffu, p, o, 16);
        if (tx == 0 && oidx >= 0) out[oidx] = p + cr;
    }
}

// ---------------- launch ----------------
extern "C" void kernel_launch(void* const* d_in, const int* in_sizes, int n_in,
                              void* d_out, int out_size) {
    const float* x0   = (const float*)d_in[0];
    const float* W1   = (const float*)d_in[1];
    const float* b1   = (const float*)d_in[2];
    const float* W2   = (const float*)d_in[3];
    const float* b2   = (const float*)d_in[4];
    const float* relW = (const float*)d_in[5];
    const int*   edge = (const int*)  d_in[6];
    const int*   rel  = (const int*)  d_in[7];
    const int*   head = (const int*)  d_in[8];
    const int*   tail = (const int*)  d_in[9];
    float*       out  = (float*)d_out;

    const int N  = in_sizes[0] / D;
    const int E  = in_sizes[6] / 2;
    const int ES = in_sizes[7];
    const int R  = in_sizes[5] / (D * D);
    const int* src = edge;
    const int* dst = edge + E;

    float *ph = nullptr, *pa = nullptr, *pT1 = nullptr, *pM = nullptr;
    cudaGetSymbolAddress((void**)&ph, g_h);
    cudaGetSymbolAddress((void**)&pa, g_a);
    cudaGetSymbolAddress((void**)&pT1, g_T1);
    cudaGetSymbolAddress((void**)&pM, g_M);

    const int T = 256;
    const int scan_blocks = (N + 8191) / 8192;
    const int agg_blocks  = (int)(((long long)N * 32 + T - 1) / T);

    static cudaStream_t s_side = nullptr;
    static cudaEvent_t  ev_fork = nullptr, ev_csr = nullptr, ev_pre = nullptr;
    static bool tried = false;
    if (!tried) {
        tried = true;
        bool ok = (cudaStreamCreateWithFlags(&s_side, cudaStreamNonBlocking) == cudaSuccess)
               && (cudaEventCreateWithFlags(&ev_fork, cudaEventDisableTiming) == cudaSuccess)
               && (cudaEventCreateWithFlags(&ev_csr,  cudaEventDisableTiming) == cudaSuccess)
               && (cudaEventCreateWithFlags(&ev_pre,  cudaEventDisableTiming) == cudaSuccess);
        if (!ok) s_side = nullptr;
    }

    if (s_side) {
        cudaEventRecord(ev_fork, 0);
        cudaStreamWaitEvent(s_side, ev_fork, 0);

        // side stream: CSR build + used-node marking (critical),
        // then relation sort + score factorization
        zero_kernel<<<(N + T - 1) / T, T, 0, s_side>>>(N);
        degmark_kernel<<<(E + T - 1) / T, T, 0, s_side>>>(dst, head, tail, E, ES);
        scan_kernel<<<scan_blocks, 1024, 0, s_side>>>(N, E);
        eperm_kernel<<<(E / 2 + T - 1) / T + 1, T, 0, s_side>>>(src, dst, E);
        cudaEventRecord(ev_csr, s_side);

        relsort_kernel<<<1, 1024, 0, s_side>>>(rel, ES);
        prep_gemm_kernel<true ><<<R, 256, 0, s_side>>>(relW, (long)D * D, W2, 0L, pT1);
        prep_gemm_kernel<false><<<R, 256, 0, s_side>>>(W2, 0L, pT1, (long)D * D, pM);
        prep_vec_kernel<<<R, 128, 0, s_side>>>(W2, relW, b2);
        cudaEventRecord(ev_pre, s_side);

        // main stream: gemm1 overlaps CSR build
        gemm_kernel<<<(N + 127) / 128, 256>>>(x0, W1, ph, N);

        cudaStreamWaitEvent(0, ev_csr, 0);
        agg_kernel<true , false, true ><<<agg_blocks, T>>>(ph, b1, pa, N); // relu_a1 = relu(b1 + Agg(h1))
        agg_kernel<false, true , false><<<agg_blocks, T>>>(pa, b1, ph, N); // t2 = Agg(relu_a1), used nodes only

        cudaStreamWaitEvent(0, ev_pre, 0);
        dim3 sgrid((ES + 127) / 128, R);
        score_gemm_kernel<<<sgrid, 256>>>(ph, head, tail, out);
    } else {
        // serial fallback
        zero_kernel<<<(N + T - 1) / T, T>>>(N);
        degmark_kernel<<<(E + T - 1) / T, T>>>(dst, head, tail, E, ES);
        scan_kernel<<<scan_blocks, 1024>>>(N, E);
        eperm_kernel<<<(E / 2 + T - 1) / T + 1, T>>>(src, dst, E);
        relsort_kernel<<<1, 1024>>>(rel, ES);
        prep_gemm_kernel<true ><<<R, 256>>>(relW, (long)D * D, W2, 0L, pT1);
        prep_gemm_kernel<false><<<R, 256>>>(W2, 0L, pT1, (long)D * D, pM);
        prep_vec_kernel<<<R, 128>>>(W2, relW, b2);
        gemm_kernel<<<(N + 127) / 128, 256>>>(x0, W1, ph, N);
        agg_kernel<true , false, true ><<<agg_blocks, T>>>(ph, b1, pa, N);
        agg_kernel<false, true , false><<<agg_blocks, T>>>(pa, b1, ph, N);
        dim3 sgrid((ES + 127) / 128, R);
        score_gemm_kernel<<<sgrid, 256>>>(ph, head, tail, out);
    }
}

// round 16
// speedup vs baseline: 2.7799x; 1.1185x over previous
#include <cuda_runtime.h>

#define D     128
#define NMAX  100000
#define EMAX  1600000
#define ESMAX 30000
#define NREL  16

// ---------------- device scratch (no allocations allowed) ----------------
__device__ float g_h[(size_t)NMAX * D];    // gemm1 out h1; later t2 = dinv*Agg(sa1)
__device__ float g_a[(size_t)NMAX * D];    // sa1 = dinv[n]*relu(b1 + dinv[n]*Agg(dinv[s]*h1))
__device__ float g_dinv[NMAX];             // d^-1/2
__device__ int   g_rowcnt[NMAX];           // in-degree counts
__device__ int   g_rowoff[NMAX + 1];       // CSR row offsets (by dst)
__device__ int   g_ncur[NMAX];             // atomic cursors for edge permutation
__device__ int   g_esrc[EMAX];             // src node per edge, sorted by dst
__device__ int   g_off[NREL + 1];
__device__ int   g_perm[ESMAX];
__device__ int   g_chain[2];               // {flag, running sum} for chained scan
__device__ unsigned char g_used[NMAX];     // nodes referenced by head/tail
// score factorization scratch
__device__ float g_T1[(size_t)NREL * D * D];   // W_r @ W2^T
__device__ float g_M [(size_t)NREL * D * D];   // W2 @ W_r @ W2^T
__device__ float g_p [NREL * D];               // W2 W_r b2
__device__ float g_q [NREL * D];               // W2 W_r^T b2
__device__ float g_c [NREL];                   // b2 W_r b2^T

// ---------------- f32x2 packed-FMA helpers ----------------
__device__ __forceinline__ unsigned long long dup2(float a) {
    unsigned long long r;
    asm("mov.b64 %0, {%1, %1};" : "=l"(r) : "f"(a));
    return r;
}
__device__ __forceinline__ void fma2(unsigned long long& c, unsigned long long a,
                                     unsigned long long b) {
    asm("fma.rn.f32x2 %0, %1, %2, %0;" : "+l"(c) : "l"(a), "l"(b));
}
__device__ __forceinline__ float2 unpack2(unsigned long long v) {
    float2 f;
    asm("mov.b64 {%0, %1}, %2;" : "=f"(f.x), "=f"(f.y) : "l"(v));
    return f;
}

// ---------------- fused zero: rowcnt + used + chain in one launch ----------------
__global__ void zero_kernel(int N) {
    int i = blockIdx.x * blockDim.x + threadIdx.x;
    if (i < N) g_rowcnt[i] = 0;
    int words = N >> 2;
    if (i < words) ((int*)g_used)[i] = 0;
    if (i == 0) {
        g_chain[0] = 0; g_chain[1] = 0;
        for (int b = words << 2; b < N; b++) g_used[b] = 0;
    }
}

// ---------------- fused degrees + used-node marking (2 items/thread) ----------------
__global__ void degmark_kernel(const int* __restrict__ dst,
                               const int* __restrict__ head,
                               const int* __restrict__ tail, int E, int ES) {
    int i = (blockIdx.x * blockDim.x + threadIdx.x) * 2;
    if (i + 1 < E) {
        int2 d2 = *(const int2*)(dst + i);
        atomicAdd(&g_rowcnt[d2.x], 1);
        atomicAdd(&g_rowcnt[d2.y], 1);
    } else if (i < E) {
        atomicAdd(&g_rowcnt[dst[i]], 1);
    }
    if (i + 1 < ES) {
        int2 h2 = *(const int2*)(head + i);
        int2 t2 = *(const int2*)(tail + i);
        g_used[h2.x] = 1; g_used[h2.y] = 1;
        g_used[t2.x] = 1; g_used[t2.y] = 1;
    } else if (i < ES) {
        g_used[head[i]] = 1;
        g_used[tail[i]] = 1;
    }
}

// single-kernel chained-lookback exclusive scan; fuses dinv + cursor init.
// 8192 items/block; all blocks co-resident (<= 13 blocks), so the spin is safe.
__global__ __launch_bounds__(1024) void scan_kernel(int N, int E) {
    __shared__ int wsum[32];
    __shared__ int wpre[32];
    __shared__ int s_base;
    const int t = threadIdx.x, b = blockIdx.x;
    const int lane = t & 31, wid = t >> 5;
    const int idx0 = b * 8192 + t * 8;

    int v[8]; int tsum = 0;
#pragma unroll
    for (int i = 0; i < 8; i++) {
        int ii = idx0 + i;
        v[i] = (ii < N) ? g_rowcnt[ii] : 0;
        tsum += v[i];
    }
    int inc = tsum;
#pragma unroll
    for (int o = 1; o < 32; o <<= 1) {
        int x = __shfl_up_sync(~0u, inc, o);
        if (lane >= o) inc += x;
    }
    if (lane == 31) wsum[wid] = inc;
    __syncthreads();
    if (wid == 0) {
        int xi = wsum[lane];
#pragma unroll
        for (int o = 1; o < 32; o <<= 1) {
            int y = __shfl_up_sync(~0u, xi, o);
            if (lane >= o) xi += y;
        }
        wpre[lane] = xi;
    }
    __syncthreads();
    const int block_total = wpre[31];
    const int thread_excl = inc - tsum + (wid > 0 ? wpre[wid - 1] : 0);

    if (t == 0) {
        while (*(volatile int*)&g_chain[0] != b) { }
        int base = g_chain[1];
        s_base = base;
        g_chain[1] = base + block_total;
        __threadfence();
        *(volatile int*)&g_chain[0] = b + 1;
    }
    __syncthreads();

    int run = s_base + thread_excl;
#pragma unroll
    for (int i = 0; i < 8; i++) {
        int ii = idx0 + i;
        if (ii < N) {
            g_rowoff[ii] = run;
            g_ncur[ii]   = run;
            g_dinv[ii]   = (v[i] > 0) ? rsqrtf((float)v[i]) : 0.0f;
        }
        run += v[i];
    }
    if (b == 0 && t == 0) g_rowoff[N] = E;
}

// group edges by dst; src index only (weights are factored out); 2 edges/thread
__global__ void eperm_kernel(const int* __restrict__ src, const int* __restrict__ dst, int E) {
    int e = (blockIdx.x * blockDim.x + threadIdx.x) * 2;
    if (e + 1 < E) {
        int2 s2 = *(const int2*)(src + e);
        int2 d2 = *(const int2*)(dst + e);
        int p0 = atomicAdd(&g_ncur[d2.x], 1);
        int p1 = atomicAdd(&g_ncur[d2.y], 1);
        g_esrc[p0] = s2.x;
        g_esrc[p1] = s2.y;
    } else if (e < E) {
        int pos = atomicAdd(&g_ncur[dst[e]], 1);
        g_esrc[pos] = src[e];
    }
}

// ---------------- fused relation counting sort (single block) ----------------
__global__ __launch_bounds__(1024) void relsort_kernel(const int* __restrict__ rel, int ES) {
    __shared__ int hist[NREL];
    const int t = threadIdx.x;
    if (t < NREL) hist[t] = 0;
    __syncthreads();
    for (int i = t; i < ES; i += 1024) atomicAdd(&hist[rel[i]], 1);
    __syncthreads();
    if (t == 0) {
        int s = 0;
        for (int r = 0; r < NREL; r++) { g_off[r] = s; int c = hist[r]; hist[r] = s; s += c; }
        g_off[NREL] = s;
    }
    __syncthreads();
    for (int i = t; i < ES; i += 1024) {
        int pos = atomicAdd(&hist[rel[i]], 1);
        g_perm[pos] = i;
    }
}

// ---------------- fp32x2 GEMM: C[M,128] = A[M,128] @ W[128,128] ----------------
__global__ __launch_bounds__(256, 2) void gemm_kernel(
    const float* __restrict__ A, const float* __restrict__ W,
    float* __restrict__ C, int M)
{
    __shared__ __align__(16) float As[32][D];   // transposed: As[k][m]
    __shared__ __align__(16) float Bs[32][D];   // Bs[k][n]
    const int tid = threadIdx.x;
    const int tx  = tid & 15;
    const int ty  = tid >> 4;
    const int base = blockIdx.x * 128;

    unsigned long long acc[8][4];
#pragma unroll
    for (int i = 0; i < 8; i++)
#pragma unroll
        for (int j = 0; j < 4; j++) acc[i][j] = 0ull;

#pragma unroll 1
    for (int kc = 0; kc < D; kc += 32) {
#pragma unroll
        for (int it = 0; it < 4; it++) {
            int idx = tid + it * 256;
            int r   = idx >> 3;
            int c4  = idx & 7;
            int gr  = base + r;
            float4 v = make_float4(0.f, 0.f, 0.f, 0.f);
            if (gr < M) v = *(const float4*)(A + (size_t)gr * D + kc + c4 * 4);
            int kk = c4 * 4;
            As[kk + 0][r] = v.x; As[kk + 1][r] = v.y;
            As[kk + 2][r] = v.z; As[kk + 3][r] = v.w;
        }
#pragma unroll
        for (int it = 0; it < 4; it++) {
            int idx = tid + it * 256;
            int k   = idx >> 5;
            int c4  = idx & 31;
            *(float4*)(&Bs[k][c4 * 4]) =
                *(const float4*)(W + (size_t)(kc + k) * D + c4 * 4);
        }
        __syncthreads();

#pragma unroll 8
        for (int k = 0; k < 32; k++) {
            float a[8];
            *(float4*)&a[0] = *(const float4*)&As[k][ty * 8];
            *(float4*)&a[4] = *(const float4*)&As[k][ty * 8 + 4];
            ulonglong2 b01 = *(const ulonglong2*)&Bs[k][tx * 8];
            ulonglong2 b23 = *(const ulonglong2*)&Bs[k][tx * 8 + 4];
#pragma unroll
            for (int i = 0; i < 8; i++) {
                unsigned long long ad = dup2(a[i]);
                fma2(acc[i][0], ad, b01.x);
                fma2(acc[i][1], ad, b01.y);
                fma2(acc[i][2], ad, b23.x);
                fma2(acc[i][3], ad, b23.y);
            }
        }
        __syncthreads();
    }

#pragma unroll
    for (int i = 0; i < 8; i++) {
        int gr = base + ty * 8 + i;
        if (gr < M) {
            float2 p0 = unpack2(acc[i][0]), p1 = unpack2(acc[i][1]);
            float2 p2 = unpack2(acc[i][2]), p3 = unpack2(acc[i][3]);
            *(float4*)(C + (size_t)gr * D + tx * 8)     = make_float4(p0.x, p0.y, p1.x, p1.y);
            *(float4*)(C + (size_t)gr * D + tx * 8 + 4) = make_float4(p2.x, p2.y, p3.x, p3.y);
        }
    }
}

// ---------------- small per-relation GEMM for score factorization ----------------
template <bool BT>
__global__ __launch_bounds__(256) void prep_gemm_kernel(
    const float* __restrict__ Abase, long astride,
    const float* __restrict__ Bbase, long bstride,
    float* __restrict__ Cbase)
{
    __shared__ __align__(16) float As[32][D];
    __shared__ __align__(16) float Bs[32][D];
    const int rrel = blockIdx.x;
    const float* A = Abase + (size_t)rrel * astride;
    const float* B = Bbase + (size_t)rrel * bstride;
    float* C = Cbase + (size_t)rrel * D * D;

    const int tid = threadIdx.x;
    const int tx  = tid & 15;
    const int ty  = tid >> 4;

    unsigned long long acc[8][4];
#pragma unroll
    for (int i = 0; i < 8; i++)
#pragma unroll
        for (int j = 0; j < 4; j++) acc[i][j] = 0ull;

#pragma unroll 1
    for (int kc = 0; kc < D; kc += 32) {
#pragma unroll
        for (int it = 0; it < 4; it++) {
            int idx = tid + it * 256;
            int r   = idx >> 3;
            int c4  = idx & 7;
            float4 v = *(const float4*)(A + (size_t)r * D + kc + c4 * 4);
            int kk = c4 * 4;
            As[kk + 0][r] = v.x; As[kk + 1][r] = v.y;
            As[kk + 2][r] = v.z; As[kk + 3][r] = v.w;
        }
        if (BT) {
#pragma unroll
            for (int it = 0; it < 4; it++) {
                int idx = tid + it * 256;
                int n   = idx >> 3;
                int c4  = idx & 7;
                float4 v = *(const float4*)(B + (size_t)n * D + kc + c4 * 4);
                int kk = c4 * 4;
                Bs[kk + 0][n] = v.x; Bs[kk + 1][n] = v.y;
                Bs[kk + 2][n] = v.z; Bs[kk + 3][n] = v.w;
            }
        } else {
#pragma unroll
            for (int it = 0; it < 4; it++) {
                int idx = tid + it * 256;
                int k   = idx >> 5;
                int c4  = idx & 31;
                *(float4*)(&Bs[k][c4 * 4]) =
                    *(const float4*)(B + (size_t)(kc + k) * D + c4 * 4);
            }
        }
        __syncthreads();

#pragma unroll 8
        for (int k = 0; k < 32; k++) {
            float a[8];
            *(float4*)&a[0] = *(const float4*)&As[k][ty * 8];
            *(float4*)&a[4] = *(const float4*)&As[k][ty * 8 + 4];
            ulonglong2 b01 = *(const ulonglong2*)&Bs[k][tx * 8];
            ulonglong2 b23 = *(const ulonglong2*)&Bs[k][tx * 8 + 4];
#pragma unroll
            for (int i = 0; i < 8; i++) {
                unsigned long long ad = dup2(a[i]);
                fma2(acc[i][0], ad, b01.x);
                fma2(acc[i][1], ad, b01.y);
                fma2(acc[i][2], ad, b23.x);
                fma2(acc[i][3], ad, b23.y);
            }
        }
        __syncthreads();
    }

#pragma unroll
    for (int i = 0; i < 8; i++) {
        int gr = ty * 8 + i;
        float2 p0 = unpack2(acc[i][0]), p1 = unpack2(acc[i][1]);
        float2 p2 = unpack2(acc[i][2]), p3 = unpack2(acc[i][3]);
        *(float4*)(C + (size_t)gr * D + tx * 8)     = make_float4(p0.x, p0.y, p1.x, p1.y);
        *(float4*)(C + (size_t)gr * D + tx * 8 + 4) = make_float4(p2.x, p2.y, p3.x, p3.y);
    }
}

// ---------------- bias cross-terms: p_r, q_r, c_r ----------------
__global__ __launch_bounds__(128) void prep_vec_kernel(
    const float* __restrict__ W2, const float* __restrict__ relW,
    const float* __restrict__ b2)
{
    __shared__ float sb2[D], s1[D], s2[D];
    __shared__ float red[4];
    const int t = threadIdx.x;
    const int r = blockIdx.x;
    sb2[t] = b2[t];
    __syncthreads();
    const float* Wr = relW + (size_t)r * D * D;
    float a1 = 0.f, a2 = 0.f;
    for (int d = 0; d < D; d++) {
        a1 += Wr[t * D + d] * sb2[d];   // s1 = W_r b2
        a2 += sb2[d] * Wr[d * D + t];   // s2 = b2 W_r
    }
    s1[t] = a1; s2[t] = a2;
    __syncthreads();
    float p = 0.f, q = 0.f;
    for (int c = 0; c < D; c++) {
        p += W2[t * D + c] * s1[c];
        q += W2[t * D + c] * s2[c];
    }
    g_p[r * D + t] = p;
    g_q[r * D + t] = q;
    float cc = a2 * sb2[t];
#pragma unroll
    for (int o = 16; o > 0; o >>= 1) cc += __shfl_down_sync(~0u, cc, o);
    if ((t & 31) == 0) red[t >> 5] = cc;
    __syncthreads();
    if (t == 0) g_c[r] = red[0] + red[1] + red[2] + red[3];
}

// ---------------- CSR aggregation (weights factored via dinv separability) ----
// LAYER1: out[n] = dinv[n]*relu(b1 + dinv[n]*sum_e dinv[src_e]*h[src_e])
// LAYER2: out[n] = dinv[n]*sum_e h[src_e]            (SPARSE: used nodes only)
template <int LAYER>
__global__ __launch_bounds__(256) void agg_kernel(
    const float* __restrict__ h, const float* __restrict__ bias,
    float* __restrict__ outb, int N)
{
    int gt   = blockIdx.x * blockDim.x + threadIdx.x;
    int node = gt >> 5;
    int lane = gt & 31;
    if (node >= N) return;
    if (LAYER == 2 && !g_used[node]) return;

    int e  = __ldg(&g_rowoff[node]);
    int e1 = __ldg(&g_rowoff[node + 1]);
    float4 acc = make_float4(0.f, 0.f, 0.f, 0.f);

    for (; e + 4 <= e1; e += 4) {
        int s0 = g_esrc[e];
        int s1 = g_esrc[e + 1];
        int s2 = g_esrc[e + 2];
        int s3 = g_esrc[e + 3];
        float4 v0 = *(const float4*)(h + (size_t)s0 * D + lane * 4);
        float4 v1 = *(const float4*)(h + (size_t)s1 * D + lane * 4);
        float4 v2 = *(const float4*)(h + (size_t)s2 * D + lane * 4);
        float4 v3 = *(const float4*)(h + (size_t)s3 * D + lane * 4);
        if (LAYER == 1) {
            float w0 = __ldg(&g_dinv[s0]), w1 = __ldg(&g_dinv[s1]);
            float w2 = __ldg(&g_dinv[s2]), w3 = __ldg(&g_dinv[s3]);
            acc.x = fmaf(w0, v0.x, acc.x); acc.y = fmaf(w0, v0.y, acc.y);
            acc.z = fmaf(w0, v0.z, acc.z); acc.w = fmaf(w0, v0.w, acc.w);
            acc.x = fmaf(w1, v1.x, acc.x); acc.y = fmaf(w1, v1.y, acc.y);
            acc.z = fmaf(w1, v1.z, acc.z); acc.w = fmaf(w1, v1.w, acc.w);
            acc.x = fmaf(w2, v2.x, acc.x); acc.y = fmaf(w2, v2.y, acc.y);
            acc.z = fmaf(w2, v2.z, acc.z); acc.w = fmaf(w2, v2.w, acc.w);
            acc.x = fmaf(w3, v3.x, acc.x); acc.y = fmaf(w3, v3.y, acc.y);
            acc.z = fmaf(w3, v3.z, acc.z); acc.w = fmaf(w3, v3.w, acc.w);
        } else {
            acc.x += v0.x + v1.x + v2.x + v3.x;
            acc.y += v0.y + v1.y + v2.y + v3.y;
            acc.z += v0.z + v1.z + v2.z + v3.z;
            acc.w += v0.w + v1.w + v2.w + v3.w;
        }
    }
    for (; e < e1; e++) {
        int s0 = g_esrc[e];
        float4 v0 = *(const float4*)(h + (size_t)s0 * D + lane * 4);
        if (LAYER == 1) {
            float w0 = __ldg(&g_dinv[s0]);
            acc.x = fmaf(w0, v0.x, acc.x); acc.y = fmaf(w0, v0.y, acc.y);
            acc.z = fmaf(w0, v0.z, acc.z); acc.w = fmaf(w0, v0.w, acc.w);
        } else {
            acc.x += v0.x; acc.y += v0.y; acc.z += v0.z; acc.w += v0.w;
        }
    }

    float dn = __ldg(&g_dinv[node]);
    if (LAYER == 1) {
        float4 bv = *(const float4*)(bias + lane * 4);
        acc.x = fmaxf(fmaf(dn, acc.x, bv.x), 0.f) * dn;
        acc.y = fmaxf(fmaf(dn, acc.y, bv.y), 0.f) * dn;
        acc.z = fmaxf(fmaf(dn, acc.z, bv.z), 0.f) * dn;
        acc.w = fmaxf(fmaf(dn, acc.w, bv.w), 0.f) * dn;
    } else {
        acc.x *= dn; acc.y *= dn; acc.z *= dn; acc.w *= dn;
    }
    *(float4*)(outb + (size_t)node * D + lane * 4) = acc;
}

// ---------------- scoring: s = th M_r tt^T + th.p_r + q_r.tt + c_r ----------------
__global__ __launch_bounds__(256, 2) void score_gemm_kernel(
    const float* __restrict__ t2,
    const int* __restrict__ head, const int* __restrict__ tail,
    float* __restrict__ out)
{
    __shared__ __align__(16) float As[32][D];
    __shared__ __align__(16) float Bs[32][D];
    __shared__ __align__(16) float sp[D];
    __shared__ __align__(16) float sq[D];
    __shared__ int sHead[128], sTail[128], sIdx[128];

    const int r     = blockIdx.y;
    const int start = g_off[r];
    const int end   = g_off[r + 1];
    const int t0    = start + blockIdx.x * 128;
    if (t0 >= end) return;

    const int tid = threadIdx.x;
    const int tx  = tid & 15;
    const int ty  = tid >> 4;

    if (tid < 128) {
        int t = t0 + tid;
        if (t < end) {
            int idx = g_perm[t];
            sIdx[tid]  = idx;
            sHead[tid] = head[idx];
            sTail[tid] = tail[idx];
        } else {
            sIdx[tid] = -1; sHead[tid] = 0; sTail[tid] = 0;
        }
        sp[tid] = g_p[r * D + tid];
        sq[tid] = g_q[r * D + tid];
    }
    __syncthreads();

    const float* Wr = g_M + (size_t)r * D * D;
    const float cr = g_c[r];

    unsigned long long acc[8][4];
#pragma unroll
    for (int i = 0; i < 8; i++)
#pragma unroll
        for (int j = 0; j < 4; j++) acc[i][j] = 0ull;

#pragma unroll 1
    for (int kc = 0; kc < D; kc += 32) {
#pragma unroll
        for (int it = 0; it < 4; it++) {
            int idx = tid + it * 256;
            int rr  = idx >> 3;
            int c4  = idx & 7;
            float4 v = *(const float4*)(t2 + (size_t)sHead[rr] * D + kc + c4 * 4);
            int kk = c4 * 4;
            As[kk + 0][rr] = v.x; As[kk + 1][rr] = v.y;
            As[kk + 2][rr] = v.z; As[kk + 3][rr] = v.w;
        }
#pragma unroll
        for (int it = 0; it < 4; it++) {
            int idx = tid + it * 256;
            int k   = idx >> 5;
            int c4  = idx & 31;
            *(float4*)(&Bs[k][c4 * 4]) =
                *(const float4*)(Wr + (size_t)(kc + k) * D + c4 * 4);
        }
        __syncthreads();

#pragma unroll 8
        for (int k = 0; k < 32; k++) {
            float a[8];
            *(float4*)&a[0] = *(const float4*)&As[k][ty * 8];
            *(float4*)&a[4] = *(const float4*)&As[k][ty * 8 + 4];
            ulonglong2 b01 = *(const ulonglong2*)&Bs[k][tx * 8];
            ulonglong2 b23 = *(const ulonglong2*)&Bs[k][tx * 8 + 4];
#pragma unroll
            for (int i = 0; i < 8; i++) {
                unsigned long long ad = dup2(a[i]);
                fma2(acc[i][0], ad, b01.x);
                fma2(acc[i][1], ad, b01.y);
                fma2(acc[i][2], ad, b23.x);
                fma2(acc[i][3], ad, b23.y);
            }
        }
        __syncthreads();
    }

    const float4 P0 = *(const float4*)&sp[tx * 8];
    const float4 P1 = *(const float4*)&sp[tx * 8 + 4];
    const float4 Q0 = *(const float4*)&sq[tx * 8];
    const float4 Q1 = *(const float4*)&sq[tx * 8 + 4];

#pragma unroll
    for (int i = 0; i < 8; i++) {
        int rr   = ty * 8 + i;
        int oidx = sIdx[rr];
        int hh   = sHead[rr];
        int tl   = sTail[rr];
        float4 z0 = *(const float4*)(t2 + (size_t)tl * D + tx * 8);
        float4 z1 = *(const float4*)(t2 + (size_t)tl * D + tx * 8 + 4);
        float4 h0 = *(const float4*)(t2 + (size_t)hh * D + tx * 8);
        float4 h1 = *(const float4*)(t2 + (size_t)hh * D + tx * 8 + 4);
        float2 p0 = unpack2(acc[i][0]), p1 = unpack2(acc[i][1]);
        float2 p2 = unpack2(acc[i][2]), p3 = unpack2(acc[i][3]);
        float p = p0.x * z0.x + p0.y * z0.y + p1.x * z0.z + p1.y * z0.w
                + p2.x * z1.x + p2.y * z1.y + p3.x * z1.z + p3.y * z1.w
                + h0.x * P0.x + h0.y * P0.y + h0.z * P0.z + h0.w * P0.w
                + h1.x * P1.x + h1.y * P1.y + h1.z * P1.z + h1.w * P1.w
                + z0.x * Q0.x + z0.y * Q0.y + z0.z * Q0.z + z0.w * Q0.w
                + z1.x * Q1.x + z1.y * Q1.y + z1.z * Q1.z + z1.w * Q1.w;
#pragma unroll
        for (int o = 8; o > 0; o >>= 1)
            p += __shfl_down_sync(0xffffffffu, p, o, 16);
        if (tx == 0 && oidx >= 0) out[oidx] = p + cr;
    }
}

// ---------------- launch ----------------
extern "C" void kernel_launch(void* const* d_in, const int* in_sizes, int n_in,
                              void* d_out, int out_size) {
    const float* x0   = (const float*)d_in[0];
    const float* W1   = (const float*)d_in[1];
    const float* b1   = (const float*)d_in[2];
    const float* W2   = (const float*)d_in[3];
    const float* b2   = (const float*)d_in[4];
    const float* relW = (const float*)d_in[5];
    const int*   edge = (const int*)  d_in[6];
    const int*   rel  = (const int*)  d_in[7];
    const int*   head = (const int*)  d_in[8];
    const int*   tail = (const int*)  d_in[9];
    float*       out  = (float*)d_out;

    const int N  = in_sizes[0] / D;
    const int E  = in_sizes[6] / 2;
    const int ES = in_sizes[7];
    const int R  = in_sizes[5] / (D * D);
    const int* src = edge;
    const int* dst = edge + E;

    float *ph = nullptr, *pa = nullptr, *pT1 = nullptr, *pM = nullptr;
    cudaGetSymbolAddress((void**)&ph, g_h);
    cudaGetSymbolAddress((void**)&pa, g_a);
    cudaGetSymbolAddress((void**)&pT1, g_T1);
    cudaGetSymbolAddress((void**)&pM, g_M);

    const int T = 256;
    const int scan_blocks = (N + 8191) / 8192;
    const int agg_blocks  = (int)(((long long)N * 32 + T - 1) / T);
    const int half_blocks = (E / 2 + T - 1) / T + 1;

    static cudaStream_t s_side = nullptr;
    static cudaEvent_t  ev_fork = nullptr, ev_csr = nullptr, ev_pre = nullptr;
    static bool tried = false;
    if (!tried) {
        tried = true;
        bool ok = (cudaStreamCreateWithFlags(&s_side, cudaStreamNonBlocking) == cudaSuccess)
               && (cudaEventCreateWithFlags(&ev_fork, cudaEventDisableTiming) == cudaSuccess)
               && (cudaEventCreateWithFlags(&ev_csr,  cudaEventDisableTiming) == cudaSuccess)
               && (cudaEventCreateWithFlags(&ev_pre,  cudaEventDisableTiming) == cudaSuccess);
        if (!ok) s_side = nullptr;
    }

    if (s_side) {
        cudaEventRecord(ev_fork, 0);
        cudaStreamWaitEvent(s_side, ev_fork, 0);

        // side stream: CSR build + used-node marking (critical),
        // then relation sort + score factorization
        zero_kernel<<<(N + T - 1) / T, T, 0, s_side>>>(N);
        degmark_kernel<<<half_blocks, T, 0, s_side>>>(dst, head, tail, E, ES);
        scan_kernel<<<scan_blocks, 1024, 0, s_side>>>(N, E);
        eperm_kernel<<<half_blocks, T, 0, s_side>>>(src, dst, E);
        cudaEventRecord(ev_csr, s_side);

        relsort_kernel<<<1, 1024, 0, s_side>>>(rel, ES);
        prep_gemm_kernel<true ><<<R, 256, 0, s_side>>>(relW, (long)D * D, W2, 0L, pT1);
        prep_gemm_kernel<false><<<R, 256, 0, s_side>>>(W2, 0L, pT1, (long)D * D, pM);
        prep_vec_kernel<<<R, 128, 0, s_side>>>(W2, relW, b2);
        cudaEventRecord(ev_pre, s_side);

        // main stream: gemm1 overlaps CSR build
        gemm_kernel<<<(N + 127) / 128, 256>>>(x0, W1, ph, N);

        cudaStreamWaitEvent(0, ev_csr, 0);
        agg_kernel<1><<<agg_blocks, T>>>(ph, b1, pa, N);   // sa1 = dinv*relu(b1 + dinv*Agg(dinv_s*h1))
        agg_kernel<2><<<agg_blocks, T>>>(pa, b1, ph, N);   // t2  = dinv*Agg(sa1), used nodes only

        cudaStreamWaitEvent(0, ev_pre, 0);
        dim3 sgrid((ES + 127) / 128, R);
        score_gemm_kernel<<<sgrid, 256>>>(ph, head, tail, out);
    } else {
        // serial fallback
        zero_kernel<<<(N + T - 1) / T, T>>>(N);
        degmark_kernel<<<half_blocks, T>>>(dst, head, tail, E, ES);
        scan_kernel<<<scan_blocks, 1024>>>(N, E);
        eperm_kernel<<<half_blocks, T>>>(src, dst, E);
        relsort_kernel<<<1, 1024>>>(rel, ES);
        prep_gemm_kernel<true ><<<R, 256>>>(relW, (long)D * D, W2, 0L, pT1);
        prep_gemm_kernel<false><<<R, 256>>>(W2, 0L, pT1, (long)D * D, pM);
        prep_vec_kernel<<<R, 128>>>(W2, relW, b2);
        gemm_kernel<<<(N + 127) / 128, 256>>>(x0, W1, ph, N);
        agg_kernel<1><<<agg_blocks, T>>>(ph, b1, pa, N);
        agg_kernel<2><<<agg_blocks, T>>>(pa, b1, ph, N);
        dim3 sgrid((ES + 127) / 128, R);
        score_gemm_kernel<<<sgrid, 256>>>(ph, head, tail, out);
    }
}